// round 6
// baseline (speedup 1.0000x reference)
#include <cuda_runtime.h>
#include <cstdint>

#define BATCH   2
#define HIMG    256
#define WIMG    256
#define CH      96
#define C3      288
#define WINSZ   16
#define SEQ     256
#define NHEADS  4
#define HD      24
#define NWIN    512
#define NTOK    131072

typedef unsigned long long ull;

__device__ float g_qkv[(size_t)NTOK * C3];
__device__ float g_o  [(size_t)NTOK * CH];

__device__ __forceinline__ ull pk2(float lo, float hi) {
    ull r; asm("mov.b64 %0, {%1,%2};" : "=l"(r) : "f"(lo), "f"(hi)); return r;
}
__device__ __forceinline__ void upk2(ull v, float& lo, float& hi) {
    asm("mov.b64 {%0,%1}, %2;" : "=f"(lo), "=f"(hi) : "l"(v));
}
__device__ __forceinline__ ull ffma2(ull a, ull b, ull c) {
    ull d; asm("fma.rn.f32x2 %0, %1, %2, %3;" : "=l"(d) : "l"(a), "l"(b), "l"(c));
    return d;
}

// ---------------------------------------------------------------------------
// GEMM: out[m, n0+n] = sum_k A[m,k]*W[k, n0+n] + bias[n0+n]
// M tile 128, N tile 48 (n0 = 48*blockIdx.y). 256 threads, 8x3 micro-tile,
// f32x2 row-pair packing. smem = 66KB -> 3 CTAs/SM (24 warps) for latency
// hiding; 12 FFMA2 vs ~22 issue slots per k keeps loop fma-bound.
// ---------------------------------------------------------------------------
#define AS_LD 128
#define BS_LD 48
#define NT    48

__global__ __launch_bounds__(256, 3)
void gemm_tok96(const float* __restrict__ A, const float* __restrict__ W,
                const float* __restrict__ bias, float* __restrict__ out,
                int wld, int oldd)
{
    extern __shared__ float sm[];
    float* As = sm;                 // [96][128]  As[k*128 + m]
    float* Bs = sm + 96 * AS_LD;    // [96][48]   Bs[k*48 + n]

    const int tid = threadIdx.x;
    const int m0  = blockIdx.x * 128;
    const int n0  = blockIdx.y * NT;

    // A tile, transposed into smem (2 threads per token row)
    {
        int m    = tid >> 1;
        int half = tid & 1;
        const float4* src = (const float4*)(A + (size_t)(m0 + m) * CH + half * 48);
        #pragma unroll
        for (int i = 0; i < 12; i++) {
            float4 v = src[i];
            int k = half * 48 + i * 4;
            As[(k + 0) * AS_LD + m] = v.x;
            As[(k + 1) * AS_LD + m] = v.y;
            As[(k + 2) * AS_LD + m] = v.z;
            As[(k + 3) * AS_LD + m] = v.w;
        }
    }
    // B tile: 96 k-rows x 48 cols = 1152 float4
    for (int idx = tid; idx < 96 * 12; idx += 256) {
        int k  = idx / 12;
        int c4 = idx - k * 12;
        float4 v = *(const float4*)(W + (size_t)k * wld + n0 + c4 * 4);
        float* dst = Bs + k * BS_LD + c4 * 4;
        dst[0] = v.x; dst[1] = v.y; dst[2] = v.z; dst[3] = v.w;
    }
    __syncthreads();

    const int ty = tid >> 4;   // rows ty*8 .. ty*8+7
    const int tx = tid & 15;   // cols tx*3 .. tx*3+2

    ull acc[4][3];
    #pragma unroll
    for (int i = 0; i < 4; i++)
        #pragma unroll
        for (int j = 0; j < 3; j++) acc[i][j] = 0ULL;

    const float* a_base = As + ty * 8;
    const float* b_base = Bs + tx * 3;

    #pragma unroll 6
    for (int k = 0; k < 96; k++) {
        const ulonglong2* ap = (const ulonglong2*)(a_base + k * AS_LD);
        ulonglong2 a01 = ap[0];
        ulonglong2 a23 = ap[1];
        ull a2[4] = { a01.x, a01.y, a23.x, a23.y };

        const float* bp = b_base + k * BS_LD;
        float b0 = bp[0], b1 = bp[1], b2v = bp[2];
        ull bb[3] = { pk2(b0, b0), pk2(b1, b1), pk2(b2v, b2v) };

        #pragma unroll
        for (int j = 0; j < 3; j++)
            #pragma unroll
            for (int i = 0; i < 4; i++) acc[i][j] = ffma2(a2[i], bb[j], acc[i][j]);
    }

    // epilogue: bias + scalar stores (warp covers 48 contiguous cols/row)
    float bvv[3];
    #pragma unroll
    for (int j = 0; j < 3; j++) bvv[j] = __ldg(bias + n0 + tx * 3 + j);

    #pragma unroll
    for (int i = 0; i < 4; i++) {
        size_t r0 = (size_t)(m0 + ty * 8 + 2 * i);
        float* o0 = out + r0 * oldd + n0 + tx * 3;
        float* o1 = out + (r0 + 1) * oldd + n0 + tx * 3;
        #pragma unroll
        for (int j = 0; j < 3; j++) {
            float l, h; upk2(acc[i][j], l, h);
            o0[j] = l + bvv[j];
            o1[j] = h + bvv[j];
        }
    }
}

// ---------------------------------------------------------------------------
// Fused attention + lepe per (window, head). 128 threads, 2 query rows each.
// occ 4 (192KB smem/SM). QK dot uses split accumulators (chain 6 not 12).
// ---------------------------------------------------------------------------
__global__ __launch_bounds__(128, 4)
void attn_lepe(const float* __restrict__ qkv, const float* __restrict__ pe_w,
               const float* __restrict__ pe_b, float* __restrict__ og)
{
    extern __shared__ float sm[];
    float* ks = sm;            // [256][24]
    float* vs = sm + SEQ * HD; // [256][24]

    const int tid = threadIdx.x;
    const int n   = blockIdx.x;
    const int h   = blockIdx.y;
    const int b   = n >> 8;
    const int wr  = (n >> 4) & 15;
    const int wc  = n & 15;
    const int rowbase = wr * 16;
    const int colbase = wc * 16;

    auto tok = [&](int s) -> int {
        int r = s >> 4, c = s & 15;
        return b * 65536 + (rowbase + r) * 256 + (colbase + c);
    };

    // stage Q through smem (coalesced), pull own rows to regs
    for (int i = tid; i < SEQ * 6; i += 128) {
        int s = i / 6, qd = i - s * 6;
        ((float4*)ks)[i] = *(const float4*)(qkv + (size_t)tok(s) * C3 + h * 72 + qd * 4);
    }
    __syncthreads();
    ull q2[2][12];
    {
        const ull* qa = (const ull*)(ks + tid * HD);
        const ull* qb = (const ull*)(ks + (tid + 128) * HD);
        #pragma unroll
        for (int i = 0; i < 12; i++) { q2[0][i] = qa[i]; q2[1][i] = qb[i]; }
    }
    __syncthreads();

    // cooperative coalesced K/V loads
    for (int i = tid; i < SEQ * 6; i += 128) {
        int s = i / 6, qd = i - s * 6;
        size_t base = (size_t)tok(s) * C3 + h * 72;
        ((float4*)ks)[i] = *(const float4*)(qkv + base + 24 + qd * 4);
        ((float4*)vs)[i] = *(const float4*)(qkv + base + 48 + qd * 4);
    }
    __syncthreads();

    const float scale = 0.20412414523193154f; // 1/sqrt(24)

    ull acc[2][12];
    #pragma unroll
    for (int i = 0; i < 12; i++) { acc[0][i] = 0ULL; acc[1][i] = 0ULL; }
    float l0 = 0.f, l1 = 0.f;

    const ulonglong2* krow = (const ulonglong2*)ks;
    const ulonglong2* vrow = (const ulonglong2*)vs;

    #pragma unroll 2
    for (int j = 0; j < SEQ; j++) {
        const ulonglong2* k4 = krow + j * 6;
        ull d0a = 0ULL, d0b = 0ULL, d1a = 0ULL, d1b = 0ULL;
        #pragma unroll
        for (int i = 0; i < 6; i++) {
            ulonglong2 kk = k4[i];
            d0a = ffma2(q2[0][2 * i],     kk.x, d0a);
            d1a = ffma2(q2[1][2 * i],     kk.x, d1a);
            d0b = ffma2(q2[0][2 * i + 1], kk.y, d0b);
            d1b = ffma2(q2[1][2 * i + 1], kk.y, d1b);
        }
        float a, bb, c, d;
        upk2(d0a, a, bb); upk2(d0b, c, d); float s0 = (a + bb + c + d) * scale;
        upk2(d1a, a, bb); upk2(d1b, c, d); float s1 = (a + bb + c + d) * scale;
        float p0 = __expf(s0), p1 = __expf(s1);
        l0 += p0; l1 += p1;
        ull p02 = pk2(p0, p0), p12 = pk2(p1, p1);
        const ulonglong2* v4 = vrow + j * 6;
        #pragma unroll
        for (int i = 0; i < 6; i++) {
            ulonglong2 vv = v4[i];
            acc[0][2 * i]     = ffma2(p02, vv.x, acc[0][2 * i]);
            acc[1][2 * i]     = ffma2(p12, vv.x, acc[1][2 * i]);
            acc[0][2 * i + 1] = ffma2(p02, vv.y, acc[0][2 * i + 1]);
            acc[1][2 * i + 1] = ffma2(p12, vv.y, acc[1][2 * i + 1]);
        }
    }

    // normalize, add lepe (3x3 depthwise on V image), store
    #pragma unroll
    for (int rr = 0; rr < 2; rr++) {
        int s = tid + rr * 128;
        float inv = 1.0f / (rr ? l1 : l0);
        float o[24];
        #pragma unroll
        for (int i = 0; i < 12; i++) {
            float lo, hi; upk2(acc[rr][i], lo, hi);
            o[2 * i]     = lo * inv;
            o[2 * i + 1] = hi * inv;
        }
        int r = s >> 4, c = s & 15;
        #pragma unroll
        for (int ky = -1; ky <= 1; ky++) {
            int r2 = r + ky;
            if (r2 < 0 || r2 > 15) continue;
            #pragma unroll
            for (int kx = -1; kx <= 1; kx++) {
                int c2 = c + kx;
                if (c2 < 0 || c2 > 15) continue;
                const float* vr = vs + (r2 * 16 + c2) * HD;
                const float* wrow = pe_w + ((ky + 1) * 3 + (kx + 1)) * CH + h * HD;
                #pragma unroll
                for (int d = 0; d < 24; d++) o[d] += vr[d] * __ldg(wrow + d);
            }
        }
        #pragma unroll
        for (int d = 0; d < 24; d++) o[d] += __ldg(pe_b + h * HD + d);

        float4* dst = (float4*)(og + (size_t)tok(s) * CH + h * HD);
        #pragma unroll
        for (int i = 0; i < 6; i++)
            dst[i] = make_float4(o[4 * i], o[4 * i + 1], o[4 * i + 2], o[4 * i + 3]);
    }
}

// ---------------------------------------------------------------------------
extern "C" void kernel_launch(void* const* d_in, const int* in_sizes, int n_in,
                              void* d_out, int out_size)
{
    const float* x     = (const float*)d_in[0];
    const float* qkv_w = (const float*)d_in[1];
    const float* qkv_b = (const float*)d_in[2];
    const float* pe_w  = (const float*)d_in[3];
    const float* pe_b  = (const float*)d_in[4];
    const float* out_w = (const float*)d_in[5];
    const float* out_b = (const float*)d_in[6];
    float* out = (float*)d_out;

    float* qkv_ptr = nullptr;
    float* o_ptr   = nullptr;
    cudaGetSymbolAddress((void**)&qkv_ptr, g_qkv);
    cudaGetSymbolAddress((void**)&o_ptr,   g_o);

    const int gemm_smem = (96 * AS_LD + 96 * BS_LD) * (int)sizeof(float); // 67584
    const int attn_smem = 2 * SEQ * HD * (int)sizeof(float);              // 49152
    cudaFuncSetAttribute(gemm_tok96, cudaFuncAttributeMaxDynamicSharedMemorySize, gemm_smem);
    cudaFuncSetAttribute(attn_lepe,  cudaFuncAttributeMaxDynamicSharedMemorySize, attn_smem);

    // 1) QKV projection: 6 N-tiles of 48 via blockIdx.y
    gemm_tok96<<<dim3(NTOK / 128, 6), 256, gemm_smem>>>(x, qkv_w, qkv_b, qkv_ptr, C3, C3);

    // 2) Fused windowed attention + lepe
    attn_lepe<<<dim3(NWIN, NHEADS), 128, attn_smem>>>(qkv_ptr, pe_w, pe_b, o_ptr);

    // 3) Output projection: 2 N-tiles of 48
    gemm_tok96<<<dim3(NTOK / 128, 2), 256, gemm_smem>>>(o_ptr, out_w, out_b, out, CH, CH);
}

// round 7
// speedup vs baseline: 1.0017x; 1.0017x over previous
#include <cuda_runtime.h>
#include <cstdint>

#define BATCH   2
#define HIMG    256
#define WIMG    256
#define CH      96
#define C3      288
#define WINSZ   16
#define SEQ     256
#define NHEADS  4
#define HD      24
#define NWIN    512
#define NTOK    131072

typedef unsigned long long ull;

__device__ float g_qkv[(size_t)NTOK * C3];
__device__ float g_o  [(size_t)NTOK * CH];

__device__ __forceinline__ ull pk2(float lo, float hi) {
    ull r; asm("mov.b64 %0, {%1,%2};" : "=l"(r) : "f"(lo), "f"(hi)); return r;
}
__device__ __forceinline__ void upk2(ull v, float& lo, float& hi) {
    asm("mov.b64 {%0,%1}, %2;" : "=f"(lo), "=f"(hi) : "l"(v));
}
__device__ __forceinline__ ull ffma2(ull a, ull b, ull c) {
    ull d; asm("fma.rn.f32x2 %0, %1, %2, %3;" : "=l"(d) : "l"(a), "l"(b), "l"(c));
    return d;
}

// ---------------------------------------------------------------------------
// GEMM: out[m, n0+n] = sum_k A[m,k]*W[k, n0+n] + bias[n0+n]
// M tile 128, N tile 48 (n0 = 48*blockIdx.y). 256 threads, 8x3 micro-tile,
// f32x2 row-pair packing. smem = 66KB -> 3 CTAs/SM (24 warps) for latency
// hiding; 12 FFMA2 vs ~22 issue slots per k keeps loop fma-bound.
// ---------------------------------------------------------------------------
#define AS_LD 128
#define BS_LD 48
#define NT    48

__global__ __launch_bounds__(256, 3)
void gemm_tok96(const float* __restrict__ A, const float* __restrict__ W,
                const float* __restrict__ bias, float* __restrict__ out,
                int wld, int oldd)
{
    extern __shared__ float sm[];
    float* As = sm;                 // [96][128]  As[k*128 + m]
    float* Bs = sm + 96 * AS_LD;    // [96][48]   Bs[k*48 + n]

    const int tid = threadIdx.x;
    const int m0  = blockIdx.x * 128;
    const int n0  = blockIdx.y * NT;

    // A tile, transposed into smem (2 threads per token row)
    {
        int m    = tid >> 1;
        int half = tid & 1;
        const float4* src = (const float4*)(A + (size_t)(m0 + m) * CH + half * 48);
        #pragma unroll
        for (int i = 0; i < 12; i++) {
            float4 v = src[i];
            int k = half * 48 + i * 4;
            As[(k + 0) * AS_LD + m] = v.x;
            As[(k + 1) * AS_LD + m] = v.y;
            As[(k + 2) * AS_LD + m] = v.z;
            As[(k + 3) * AS_LD + m] = v.w;
        }
    }
    // B tile: 96 k-rows x 48 cols = 1152 float4
    for (int idx = tid; idx < 96 * 12; idx += 256) {
        int k  = idx / 12;
        int c4 = idx - k * 12;
        float4 v = *(const float4*)(W + (size_t)k * wld + n0 + c4 * 4);
        float* dst = Bs + k * BS_LD + c4 * 4;
        dst[0] = v.x; dst[1] = v.y; dst[2] = v.z; dst[3] = v.w;
    }
    __syncthreads();

    const int ty = tid >> 4;   // rows ty*8 .. ty*8+7
    const int tx = tid & 15;   // cols tx*3 .. tx*3+2

    ull acc[4][3];
    #pragma unroll
    for (int i = 0; i < 4; i++)
        #pragma unroll
        for (int j = 0; j < 3; j++) acc[i][j] = 0ULL;

    const float* a_base = As + ty * 8;
    const float* b_base = Bs + tx * 3;

    #pragma unroll 6
    for (int k = 0; k < 96; k++) {
        const ulonglong2* ap = (const ulonglong2*)(a_base + k * AS_LD);
        ulonglong2 a01 = ap[0];
        ulonglong2 a23 = ap[1];
        ull a2[4] = { a01.x, a01.y, a23.x, a23.y };

        const float* bp = b_base + k * BS_LD;
        float b0 = bp[0], b1 = bp[1], b2v = bp[2];
        ull bb[3] = { pk2(b0, b0), pk2(b1, b1), pk2(b2v, b2v) };

        #pragma unroll
        for (int j = 0; j < 3; j++)
            #pragma unroll
            for (int i = 0; i < 4; i++) acc[i][j] = ffma2(a2[i], bb[j], acc[i][j]);
    }

    // epilogue: bias + scalar stores (warp covers 48 contiguous cols/row)
    float bvv[3];
    #pragma unroll
    for (int j = 0; j < 3; j++) bvv[j] = __ldg(bias + n0 + tx * 3 + j);

    #pragma unroll
    for (int i = 0; i < 4; i++) {
        size_t r0 = (size_t)(m0 + ty * 8 + 2 * i);
        float* o0 = out + r0 * oldd + n0 + tx * 3;
        float* o1 = out + (r0 + 1) * oldd + n0 + tx * 3;
        #pragma unroll
        for (int j = 0; j < 3; j++) {
            float l, h; upk2(acc[i][j], l, h);
            o0[j] = l + bvv[j];
            o1[j] = h + bvv[j];
        }
    }
}

// ---------------------------------------------------------------------------
// Fused attention + lepe per (window, head). 128 threads, 2 query rows each.
// occ 4 (192KB smem/SM). QK dot uses split accumulators (chain 6 not 12).
// ---------------------------------------------------------------------------
__global__ __launch_bounds__(128, 4)
void attn_lepe(const float* __restrict__ qkv, const float* __restrict__ pe_w,
               const float* __restrict__ pe_b, float* __restrict__ og)
{
    extern __shared__ float sm[];
    float* ks = sm;            // [256][24]
    float* vs = sm + SEQ * HD; // [256][24]

    const int tid = threadIdx.x;
    const int n   = blockIdx.x;
    const int h   = blockIdx.y;
    const int b   = n >> 8;
    const int wr  = (n >> 4) & 15;
    const int wc  = n & 15;
    const int rowbase = wr * 16;
    const int colbase = wc * 16;

    auto tok = [&](int s) -> int {
        int r = s >> 4, c = s & 15;
        return b * 65536 + (rowbase + r) * 256 + (colbase + c);
    };

    // stage Q through smem (coalesced), pull own rows to regs
    for (int i = tid; i < SEQ * 6; i += 128) {
        int s = i / 6, qd = i - s * 6;
        ((float4*)ks)[i] = *(const float4*)(qkv + (size_t)tok(s) * C3 + h * 72 + qd * 4);
    }
    __syncthreads();
    ull q2[2][12];
    {
        const ull* qa = (const ull*)(ks + tid * HD);
        const ull* qb = (const ull*)(ks + (tid + 128) * HD);
        #pragma unroll
        for (int i = 0; i < 12; i++) { q2[0][i] = qa[i]; q2[1][i] = qb[i]; }
    }
    __syncthreads();

    // cooperative coalesced K/V loads
    for (int i = tid; i < SEQ * 6; i += 128) {
        int s = i / 6, qd = i - s * 6;
        size_t base = (size_t)tok(s) * C3 + h * 72;
        ((float4*)ks)[i] = *(const float4*)(qkv + base + 24 + qd * 4);
        ((float4*)vs)[i] = *(const float4*)(qkv + base + 48 + qd * 4);
    }
    __syncthreads();

    const float scale = 0.20412414523193154f; // 1/sqrt(24)

    ull acc[2][12];
    #pragma unroll
    for (int i = 0; i < 12; i++) { acc[0][i] = 0ULL; acc[1][i] = 0ULL; }
    float l0 = 0.f, l1 = 0.f;

    const ulonglong2* krow = (const ulonglong2*)ks;
    const ulonglong2* vrow = (const ulonglong2*)vs;

    #pragma unroll 2
    for (int j = 0; j < SEQ; j++) {
        const ulonglong2* k4 = krow + j * 6;
        ull d0a = 0ULL, d0b = 0ULL, d1a = 0ULL, d1b = 0ULL;
        #pragma unroll
        for (int i = 0; i < 6; i++) {
            ulonglong2 kk = k4[i];
            d0a = ffma2(q2[0][2 * i],     kk.x, d0a);
            d1a = ffma2(q2[1][2 * i],     kk.x, d1a);
            d0b = ffma2(q2[0][2 * i + 1], kk.y, d0b);
            d1b = ffma2(q2[1][2 * i + 1], kk.y, d1b);
        }
        float a, bb, c, d;
        upk2(d0a, a, bb); upk2(d0b, c, d); float s0 = (a + bb + c + d) * scale;
        upk2(d1a, a, bb); upk2(d1b, c, d); float s1 = (a + bb + c + d) * scale;
        float p0 = __expf(s0), p1 = __expf(s1);
        l0 += p0; l1 += p1;
        ull p02 = pk2(p0, p0), p12 = pk2(p1, p1);
        const ulonglong2* v4 = vrow + j * 6;
        #pragma unroll
        for (int i = 0; i < 6; i++) {
            ulonglong2 vv = v4[i];
            acc[0][2 * i]     = ffma2(p02, vv.x, acc[0][2 * i]);
            acc[1][2 * i]     = ffma2(p12, vv.x, acc[1][2 * i]);
            acc[0][2 * i + 1] = ffma2(p02, vv.y, acc[0][2 * i + 1]);
            acc[1][2 * i + 1] = ffma2(p12, vv.y, acc[1][2 * i + 1]);
        }
    }

    // normalize, add lepe (3x3 depthwise on V image), store
    #pragma unroll
    for (int rr = 0; rr < 2; rr++) {
        int s = tid + rr * 128;
        float inv = 1.0f / (rr ? l1 : l0);
        float o[24];
        #pragma unroll
        for (int i = 0; i < 12; i++) {
            float lo, hi; upk2(acc[rr][i], lo, hi);
            o[2 * i]     = lo * inv;
            o[2 * i + 1] = hi * inv;
        }
        int r = s >> 4, c = s & 15;
        #pragma unroll
        for (int ky = -1; ky <= 1; ky++) {
            int r2 = r + ky;
            if (r2 < 0 || r2 > 15) continue;
            #pragma unroll
            for (int kx = -1; kx <= 1; kx++) {
                int c2 = c + kx;
                if (c2 < 0 || c2 > 15) continue;
                const float* vr = vs + (r2 * 16 + c2) * HD;
                const float* wrow = pe_w + ((ky + 1) * 3 + (kx + 1)) * CH + h * HD;
                #pragma unroll
                for (int d = 0; d < 24; d++) o[d] += vr[d] * __ldg(wrow + d);
            }
        }
        #pragma unroll
        for (int d = 0; d < 24; d++) o[d] += __ldg(pe_b + h * HD + d);

        float4* dst = (float4*)(og + (size_t)tok(s) * CH + h * HD);
        #pragma unroll
        for (int i = 0; i < 6; i++)
            dst[i] = make_float4(o[4 * i], o[4 * i + 1], o[4 * i + 2], o[4 * i + 3]);
    }
}

// ---------------------------------------------------------------------------
extern "C" void kernel_launch(void* const* d_in, const int* in_sizes, int n_in,
                              void* d_out, int out_size)
{
    const float* x     = (const float*)d_in[0];
    const float* qkv_w = (const float*)d_in[1];
    const float* qkv_b = (const float*)d_in[2];
    const float* pe_w  = (const float*)d_in[3];
    const float* pe_b  = (const float*)d_in[4];
    const float* out_w = (const float*)d_in[5];
    const float* out_b = (const float*)d_in[6];
    float* out = (float*)d_out;

    float* qkv_ptr = nullptr;
    float* o_ptr   = nullptr;
    cudaGetSymbolAddress((void**)&qkv_ptr, g_qkv);
    cudaGetSymbolAddress((void**)&o_ptr,   g_o);

    const int gemm_smem = (96 * AS_LD + 96 * BS_LD) * (int)sizeof(float); // 67584
    const int attn_smem = 2 * SEQ * HD * (int)sizeof(float);              // 49152
    cudaFuncSetAttribute(gemm_tok96, cudaFuncAttributeMaxDynamicSharedMemorySize, gemm_smem);
    cudaFuncSetAttribute(attn_lepe,  cudaFuncAttributeMaxDynamicSharedMemorySize, attn_smem);

    // 1) QKV projection: 6 N-tiles of 48 via blockIdx.y
    gemm_tok96<<<dim3(NTOK / 128, 6), 256, gemm_smem>>>(x, qkv_w, qkv_b, qkv_ptr, C3, C3);

    // 2) Fused windowed attention + lepe
    attn_lepe<<<dim3(NWIN, NHEADS), 128, attn_smem>>>(qkv_ptr, pe_w, pe_b, o_ptr);

    // 3) Output projection: 2 N-tiles of 48
    gemm_tok96<<<dim3(NTOK / 128, 2), 256, gemm_smem>>>(o_ptr, out_w, out_b, out, CH, CH);
}

// round 8
// speedup vs baseline: 1.0021x; 1.0003x over previous
#include <cuda_runtime.h>
#include <cstdint>

#define BATCH   2
#define HIMG    256
#define WIMG    256
#define CH      96
#define C3      288
#define WINSZ   16
#define SEQ     256
#define NHEADS  4
#define HD      24
#define NWIN    512
#define NTOK    131072

typedef unsigned long long ull;

__device__ float g_qkv[(size_t)NTOK * C3];
__device__ float g_o  [(size_t)NTOK * CH];

__device__ __forceinline__ ull pk2(float lo, float hi) {
    ull r; asm("mov.b64 %0, {%1,%2};" : "=l"(r) : "f"(lo), "f"(hi)); return r;
}
__device__ __forceinline__ void upk2(ull v, float& lo, float& hi) {
    asm("mov.b64 {%0,%1}, %2;" : "=f"(lo), "=f"(hi) : "l"(v));
}
__device__ __forceinline__ ull ffma2(ull a, ull b, ull c) {
    ull d; asm("fma.rn.f32x2 %0, %1, %2, %3;" : "=l"(d) : "l"(a), "l"(b), "l"(c));
    return d;
}

// ---------------------------------------------------------------------------
// GEMM: out[m, n0+n] = sum_k A[m,k]*W[k, n0+n] + bias[n0+n]
// M tile 128, N tile 48 (n0 = 48*blockIdx.y). 256 threads, 8x3 micro-tile,
// f32x2 row-pair packing. smem = 66KB -> 3 CTAs/SM (24 warps) for latency
// hiding; 12 FFMA2 vs ~22 issue slots per k keeps loop fma-bound.
// ---------------------------------------------------------------------------
#define AS_LD 128
#define BS_LD 48
#define NT    48

__global__ __launch_bounds__(256, 3)
void gemm_tok96(const float* __restrict__ A, const float* __restrict__ W,
                const float* __restrict__ bias, float* __restrict__ out,
                int wld, int oldd)
{
    extern __shared__ float sm[];
    float* As = sm;                 // [96][128]  As[k*128 + m]
    float* Bs = sm + 96 * AS_LD;    // [96][48]   Bs[k*48 + n]

    const int tid = threadIdx.x;
    const int m0  = blockIdx.x * 128;
    const int n0  = blockIdx.y * NT;

    // A tile, transposed into smem (2 threads per token row)
    {
        int m    = tid >> 1;
        int half = tid & 1;
        const float4* src = (const float4*)(A + (size_t)(m0 + m) * CH + half * 48);
        #pragma unroll
        for (int i = 0; i < 12; i++) {
            float4 v = src[i];
            int k = half * 48 + i * 4;
            As[(k + 0) * AS_LD + m] = v.x;
            As[(k + 1) * AS_LD + m] = v.y;
            As[(k + 2) * AS_LD + m] = v.z;
            As[(k + 3) * AS_LD + m] = v.w;
        }
    }
    // B tile: 96 k-rows x 48 cols = 1152 float4
    for (int idx = tid; idx < 96 * 12; idx += 256) {
        int k  = idx / 12;
        int c4 = idx - k * 12;
        float4 v = *(const float4*)(W + (size_t)k * wld + n0 + c4 * 4);
        float* dst = Bs + k * BS_LD + c4 * 4;
        dst[0] = v.x; dst[1] = v.y; dst[2] = v.z; dst[3] = v.w;
    }
    __syncthreads();

    const int ty = tid >> 4;   // rows ty*8 .. ty*8+7
    const int tx = tid & 15;   // cols tx*3 .. tx*3+2

    ull acc[4][3];
    #pragma unroll
    for (int i = 0; i < 4; i++)
        #pragma unroll
        for (int j = 0; j < 3; j++) acc[i][j] = 0ULL;

    const float* a_base = As + ty * 8;
    const float* b_base = Bs + tx * 3;

    #pragma unroll 6
    for (int k = 0; k < 96; k++) {
        const ulonglong2* ap = (const ulonglong2*)(a_base + k * AS_LD);
        ulonglong2 a01 = ap[0];
        ulonglong2 a23 = ap[1];
        ull a2[4] = { a01.x, a01.y, a23.x, a23.y };

        const float* bp = b_base + k * BS_LD;
        float b0 = bp[0], b1 = bp[1], b2v = bp[2];
        ull bb[3] = { pk2(b0, b0), pk2(b1, b1), pk2(b2v, b2v) };

        #pragma unroll
        for (int j = 0; j < 3; j++)
            #pragma unroll
            for (int i = 0; i < 4; i++) acc[i][j] = ffma2(a2[i], bb[j], acc[i][j]);
    }

    // epilogue: bias + scalar stores (warp covers 48 contiguous cols/row)
    float bvv[3];
    #pragma unroll
    for (int j = 0; j < 3; j++) bvv[j] = __ldg(bias + n0 + tx * 3 + j);

    #pragma unroll
    for (int i = 0; i < 4; i++) {
        size_t r0 = (size_t)(m0 + ty * 8 + 2 * i);
        float* o0 = out + r0 * oldd + n0 + tx * 3;
        float* o1 = out + (r0 + 1) * oldd + n0 + tx * 3;
        #pragma unroll
        for (int j = 0; j < 3; j++) {
            float l, h; upk2(acc[i][j], l, h);
            o0[j] = l + bvv[j];
            o1[j] = h + bvv[j];
        }
    }
}

// ---------------------------------------------------------------------------
// Fused attention + lepe per (window, head). 128 threads, 2 query rows each.
// occ 4 (192KB smem/SM). QK dot uses split accumulators (chain 6 not 12).
// ---------------------------------------------------------------------------
__global__ __launch_bounds__(128, 4)
void attn_lepe(const float* __restrict__ qkv, const float* __restrict__ pe_w,
               const float* __restrict__ pe_b, float* __restrict__ og)
{
    extern __shared__ float sm[];
    float* ks = sm;            // [256][24]
    float* vs = sm + SEQ * HD; // [256][24]

    const int tid = threadIdx.x;
    const int n   = blockIdx.x;
    const int h   = blockIdx.y;
    const int b   = n >> 8;
    const int wr  = (n >> 4) & 15;
    const int wc  = n & 15;
    const int rowbase = wr * 16;
    const int colbase = wc * 16;

    auto tok = [&](int s) -> int {
        int r = s >> 4, c = s & 15;
        return b * 65536 + (rowbase + r) * 256 + (colbase + c);
    };

    // stage Q through smem (coalesced), pull own rows to regs
    for (int i = tid; i < SEQ * 6; i += 128) {
        int s = i / 6, qd = i - s * 6;
        ((float4*)ks)[i] = *(const float4*)(qkv + (size_t)tok(s) * C3 + h * 72 + qd * 4);
    }
    __syncthreads();
    ull q2[2][12];
    {
        const ull* qa = (const ull*)(ks + tid * HD);
        const ull* qb = (const ull*)(ks + (tid + 128) * HD);
        #pragma unroll
        for (int i = 0; i < 12; i++) { q2[0][i] = qa[i]; q2[1][i] = qb[i]; }
    }
    __syncthreads();

    // cooperative coalesced K/V loads
    for (int i = tid; i < SEQ * 6; i += 128) {
        int s = i / 6, qd = i - s * 6;
        size_t base = (size_t)tok(s) * C3 + h * 72;
        ((float4*)ks)[i] = *(const float4*)(qkv + base + 24 + qd * 4);
        ((float4*)vs)[i] = *(const float4*)(qkv + base + 48 + qd * 4);
    }
    __syncthreads();

    const float scale = 0.20412414523193154f; // 1/sqrt(24)

    ull acc[2][12];
    #pragma unroll
    for (int i = 0; i < 12; i++) { acc[0][i] = 0ULL; acc[1][i] = 0ULL; }
    float l0 = 0.f, l1 = 0.f;

    const ulonglong2* krow = (const ulonglong2*)ks;
    const ulonglong2* vrow = (const ulonglong2*)vs;

    #pragma unroll 2
    for (int j = 0; j < SEQ; j++) {
        const ulonglong2* k4 = krow + j * 6;
        ull d0a = 0ULL, d0b = 0ULL, d1a = 0ULL, d1b = 0ULL;
        #pragma unroll
        for (int i = 0; i < 6; i++) {
            ulonglong2 kk = k4[i];
            d0a = ffma2(q2[0][2 * i],     kk.x, d0a);
            d1a = ffma2(q2[1][2 * i],     kk.x, d1a);
            d0b = ffma2(q2[0][2 * i + 1], kk.y, d0b);
            d1b = ffma2(q2[1][2 * i + 1], kk.y, d1b);
        }
        float a, bb, c, d;
        upk2(d0a, a, bb); upk2(d0b, c, d); float s0 = (a + bb + c + d) * scale;
        upk2(d1a, a, bb); upk2(d1b, c, d); float s1 = (a + bb + c + d) * scale;
        float p0 = __expf(s0), p1 = __expf(s1);
        l0 += p0; l1 += p1;
        ull p02 = pk2(p0, p0), p12 = pk2(p1, p1);
        const ulonglong2* v4 = vrow + j * 6;
        #pragma unroll
        for (int i = 0; i < 6; i++) {
            ulonglong2 vv = v4[i];
            acc[0][2 * i]     = ffma2(p02, vv.x, acc[0][2 * i]);
            acc[1][2 * i]     = ffma2(p12, vv.x, acc[1][2 * i]);
            acc[0][2 * i + 1] = ffma2(p02, vv.y, acc[0][2 * i + 1]);
            acc[1][2 * i + 1] = ffma2(p12, vv.y, acc[1][2 * i + 1]);
        }
    }

    // normalize, add lepe (3x3 depthwise on V image), store
    #pragma unroll
    for (int rr = 0; rr < 2; rr++) {
        int s = tid + rr * 128;
        float inv = 1.0f / (rr ? l1 : l0);
        float o[24];
        #pragma unroll
        for (int i = 0; i < 12; i++) {
            float lo, hi; upk2(acc[rr][i], lo, hi);
            o[2 * i]     = lo * inv;
            o[2 * i + 1] = hi * inv;
        }
        int r = s >> 4, c = s & 15;
        #pragma unroll
        for (int ky = -1; ky <= 1; ky++) {
            int r2 = r + ky;
            if (r2 < 0 || r2 > 15) continue;
            #pragma unroll
            for (int kx = -1; kx <= 1; kx++) {
                int c2 = c + kx;
                if (c2 < 0 || c2 > 15) continue;
                const float* vr = vs + (r2 * 16 + c2) * HD;
                const float* wrow = pe_w + ((ky + 1) * 3 + (kx + 1)) * CH + h * HD;
                #pragma unroll
                for (int d = 0; d < 24; d++) o[d] += vr[d] * __ldg(wrow + d);
            }
        }
        #pragma unroll
        for (int d = 0; d < 24; d++) o[d] += __ldg(pe_b + h * HD + d);

        float4* dst = (float4*)(og + (size_t)tok(s) * CH + h * HD);
        #pragma unroll
        for (int i = 0; i < 6; i++)
            dst[i] = make_float4(o[4 * i], o[4 * i + 1], o[4 * i + 2], o[4 * i + 3]);
    }
}

// ---------------------------------------------------------------------------
extern "C" void kernel_launch(void* const* d_in, const int* in_sizes, int n_in,
                              void* d_out, int out_size)
{
    const float* x     = (const float*)d_in[0];
    const float* qkv_w = (const float*)d_in[1];
    const float* qkv_b = (const float*)d_in[2];
    const float* pe_w  = (const float*)d_in[3];
    const float* pe_b  = (const float*)d_in[4];
    const float* out_w = (const float*)d_in[5];
    const float* out_b = (const float*)d_in[6];
    float* out = (float*)d_out;

    float* qkv_ptr = nullptr;
    float* o_ptr   = nullptr;
    cudaGetSymbolAddress((void**)&qkv_ptr, g_qkv);
    cudaGetSymbolAddress((void**)&o_ptr,   g_o);

    const int gemm_smem = (96 * AS_LD + 96 * BS_LD) * (int)sizeof(float); // 67584
    const int attn_smem = 2 * SEQ * HD * (int)sizeof(float);              // 49152
    cudaFuncSetAttribute(gemm_tok96, cudaFuncAttributeMaxDynamicSharedMemorySize, gemm_smem);
    cudaFuncSetAttribute(attn_lepe,  cudaFuncAttributeMaxDynamicSharedMemorySize, attn_smem);

    // 1) QKV projection: 6 N-tiles of 48 via blockIdx.y
    gemm_tok96<<<dim3(NTOK / 128, 6), 256, gemm_smem>>>(x, qkv_w, qkv_b, qkv_ptr, C3, C3);

    // 2) Fused windowed attention + lepe
    attn_lepe<<<dim3(NWIN, NHEADS), 128, attn_smem>>>(qkv_ptr, pe_w, pe_b, o_ptr);

    // 3) Output projection: 2 N-tiles of 48
    gemm_tok96<<<dim3(NTOK / 128, 2), 256, gemm_smem>>>(o_ptr, out_w, out_b, out, CH, CH);
}

// round 10
// speedup vs baseline: 1.1101x; 1.1078x over previous
#include <cuda_runtime.h>
#include <cuda_bf16.h>
#include <cstdint>

#define BATCH   2
#define HIMG    256
#define WIMG    256
#define CH      96
#define C3      288
#define WINSZ   16
#define SEQ     256
#define NHEADS  4
#define HD      24
#define NWIN    512
#define NTOK    131072

typedef unsigned long long ull;

__device__ float g_qkv[(size_t)NTOK * C3];
__device__ float g_o  [(size_t)NTOK * CH];

// ---------------- f32x2 helpers (attention) ---------------------------------
__device__ __forceinline__ ull pk2(float lo, float hi) {
    ull r; asm("mov.b64 %0, {%1,%2};" : "=l"(r) : "f"(lo), "f"(hi)); return r;
}
__device__ __forceinline__ void upk2(ull v, float& lo, float& hi) {
    asm("mov.b64 {%0,%1}, %2;" : "=f"(lo), "=f"(hi) : "l"(v));
}
__device__ __forceinline__ ull ffma2(ull a, ull b, ull c) {
    ull d; asm("fma.rn.f32x2 %0, %1, %2, %3;" : "=l"(d) : "l"(a), "l"(b), "l"(c));
    return d;
}

// ---------------- mma helpers ------------------------------------------------
__device__ __forceinline__ uint32_t smem_u32(const void* p) {
    uint32_t a;
    asm("{ .reg .u64 t; cvta.to.shared.u64 t, %1; cvt.u32.u64 %0, t; }" : "=r"(a) : "l"(p));
    return a;
}
__device__ __forceinline__ void ldm_x4(uint32_t addr, uint32_t& r0, uint32_t& r1,
                                       uint32_t& r2, uint32_t& r3) {
    asm volatile("ldmatrix.sync.aligned.m8n8.x4.shared.b16 {%0,%1,%2,%3}, [%4];"
                 : "=r"(r0), "=r"(r1), "=r"(r2), "=r"(r3) : "r"(addr));
}
__device__ __forceinline__ void mma_bf16(float* c, const uint32_t* a, const uint32_t* b) {
    asm volatile(
        "mma.sync.aligned.m16n8k16.row.col.f32.bf16.bf16.f32 "
        "{%0,%1,%2,%3}, {%4,%5,%6,%7}, {%8,%9}, {%0,%1,%2,%3};"
        : "+f"(c[0]), "+f"(c[1]), "+f"(c[2]), "+f"(c[3])
        : "r"(a[0]), "r"(a[1]), "r"(a[2]), "r"(a[3]), "r"(b[0]), "r"(b[1]));
}
__device__ __forceinline__ void bf16split(float v, __nv_bfloat16& h, __nv_bfloat16& l) {
    h = __float2bfloat16(v);
    l = __float2bfloat16(v - __bfloat162float(h));
}

// ---------------------------------------------------------------------------
// Tensor-core GEMM (mma.sync bf16, 3-term split): out = A[128,96] @ W[96,96] + b
// Block 256 thr (8 warps, 4x2), warp tile 32x48 (2x6 m16n8k16 tiles).
// A/B converted once to bf16 hi/lo smem planes, pitch 104 bf16 (208B,
// ldmatrix-conflict-free). K = 6 chunks of 16; 3 MMAs per (mt,nt,chunk).
// ---------------------------------------------------------------------------
#define PITCH 104

__global__ __launch_bounds__(256, 2)
void gemm_mma(const float* __restrict__ A, const float* __restrict__ W,
              const float* __restrict__ bias, float* __restrict__ out,
              int wld, int oldd)
{
    extern __shared__ __nv_bfloat16 smbf[];
    __nv_bfloat16* Ahi = smbf;                    // [128][104]
    __nv_bfloat16* Alo = Ahi + 128 * PITCH;
    __nv_bfloat16* Bhi = Alo + 128 * PITCH;       // [96][104]  ([n][k])
    __nv_bfloat16* Blo = Bhi + 96 * PITCH;

    const int tid  = threadIdx.x;
    const int lane = tid & 31;
    const int wid  = tid >> 5;
    const int m0   = blockIdx.x * 128;
    const int n0   = blockIdx.y * 96;

    // ---- convert A tile: 128 rows x 96 floats -> hi/lo bf16 ----
    for (int idx = tid; idx < 128 * 24; idx += 256) {
        int m = idx / 24, q = idx - m * 24;
        float4 v = *(const float4*)(A + (size_t)(m0 + m) * CH + q * 4);
        __nv_bfloat16 h, l;
        __nv_bfloat16* ah = Ahi + m * PITCH + q * 4;
        __nv_bfloat16* al = Alo + m * PITCH + q * 4;
        bf16split(v.x, h, l); ah[0] = h; al[0] = l;
        bf16split(v.y, h, l); ah[1] = h; al[1] = l;
        bf16split(v.z, h, l); ah[2] = h; al[2] = l;
        bf16split(v.w, h, l); ah[3] = h; al[3] = l;
    }
    // ---- convert B tile: W[k][n0+n] -> Bs[n][k] hi/lo ----
    for (int idx = tid; idx < 96 * 24; idx += 256) {
        int k = idx / 24, q = idx - k * 24;
        float4 v = *(const float4*)(W + (size_t)k * wld + n0 + q * 4);
        __nv_bfloat16 h, l;
        int n = q * 4;
        bf16split(v.x, h, l); Bhi[(n + 0) * PITCH + k] = h; Blo[(n + 0) * PITCH + k] = l;
        bf16split(v.y, h, l); Bhi[(n + 1) * PITCH + k] = h; Blo[(n + 1) * PITCH + k] = l;
        bf16split(v.z, h, l); Bhi[(n + 2) * PITCH + k] = h; Blo[(n + 2) * PITCH + k] = l;
        bf16split(v.w, h, l); Bhi[(n + 3) * PITCH + k] = h; Blo[(n + 3) * PITCH + k] = l;
    }
    __syncthreads();

    const int warp_m = wid & 3;    // 0..3 -> m offset 32*warp_m
    const int warp_n = wid >> 2;   // 0..1 -> n offset 48*warp_n

    // ldmatrix thread->address mappings
    // A (m16k16 x4): row = warp_m*32 + mt*16 + (lane&15), kblk = (lane>>4)*8
    const uint32_t a_row  = warp_m * 32 + (lane & 15);
    const uint32_t a_koff = (lane >> 4) * 8;
    uint32_t aHi0 = smem_u32(Ahi + a_row * PITCH + a_koff);
    uint32_t aLo0 = smem_u32(Alo + a_row * PITCH + a_koff);
    // B (two n-tiles per x4): nrow = p*16 + (lane&7) + ((lane>>4)<<3), kblk = ((lane>>3)&1)*8
    const uint32_t b_nrow = warp_n * 48 + (lane & 7) + ((lane >> 4) << 3);
    const uint32_t b_koff = ((lane >> 3) & 1) * 8;
    uint32_t bHi0 = smem_u32(Bhi + b_nrow * PITCH + b_koff);
    uint32_t bLo0 = smem_u32(Blo + b_nrow * PITCH + b_koff);

    float acc[2][6][4];
    #pragma unroll
    for (int i = 0; i < 2; i++)
        #pragma unroll
        for (int j = 0; j < 6; j++)
            #pragma unroll
            for (int q = 0; q < 4; q++) acc[i][j][q] = 0.f;

    #pragma unroll
    for (int c = 0; c < 6; c++) {
        const uint32_t kb = c * 32;   // 16 bf16 = 32 bytes per chunk

        uint32_t ahi[2][4], alo[2][4];
        #pragma unroll
        for (int mt = 0; mt < 2; mt++) {
            ldm_x4(aHi0 + mt * (16 * PITCH * 2) + kb,
                   ahi[mt][0], ahi[mt][1], ahi[mt][2], ahi[mt][3]);
            ldm_x4(aLo0 + mt * (16 * PITCH * 2) + kb,
                   alo[mt][0], alo[mt][1], alo[mt][2], alo[mt][3]);
        }
        uint32_t bhi[6][2], blo[6][2];
        #pragma unroll
        for (int p = 0; p < 3; p++) {
            ldm_x4(bHi0 + p * (16 * PITCH * 2) + kb,
                   bhi[2 * p][0], bhi[2 * p][1], bhi[2 * p + 1][0], bhi[2 * p + 1][1]);
            ldm_x4(bLo0 + p * (16 * PITCH * 2) + kb,
                   blo[2 * p][0], blo[2 * p][1], blo[2 * p + 1][0], blo[2 * p + 1][1]);
        }

        #pragma unroll
        for (int nt = 0; nt < 6; nt++)
            #pragma unroll
            for (int mt = 0; mt < 2; mt++) {
                mma_bf16(acc[mt][nt], ahi[mt], bhi[nt]);   // hi*hi
                mma_bf16(acc[mt][nt], ahi[mt], blo[nt]);   // hi*lo
                mma_bf16(acc[mt][nt], alo[mt], bhi[nt]);   // lo*hi
            }
    }

    // ---- epilogue: bias + float2 stores ----
    #pragma unroll
    for (int nt = 0; nt < 6; nt++) {
        int col = n0 + warp_n * 48 + nt * 8 + (lane & 3) * 2;
        float b0 = __ldg(bias + col), b1 = __ldg(bias + col + 1);
        #pragma unroll
        for (int mt = 0; mt < 2; mt++) {
            int row0 = m0 + warp_m * 32 + mt * 16 + (lane >> 2);
            float2 v0 = make_float2(acc[mt][nt][0] + b0, acc[mt][nt][1] + b1);
            float2 v1 = make_float2(acc[mt][nt][2] + b0, acc[mt][nt][3] + b1);
            *(float2*)(out + (size_t)row0 * oldd + col)       = v0;
            *(float2*)(out + (size_t)(row0 + 8) * oldd + col) = v1;
        }
    }
}

#define GEMM_MMA_SMEM ((2 * 128 * PITCH + 2 * 96 * PITCH) * (int)sizeof(__nv_bfloat16)) // 93184

// ---------------------------------------------------------------------------
// Fused attention + lepe per (window, head). 128 threads, 2 query rows each.
// (unchanged from R8)
// ---------------------------------------------------------------------------
__global__ __launch_bounds__(128, 4)
void attn_lepe(const float* __restrict__ qkv, const float* __restrict__ pe_w,
               const float* __restrict__ pe_b, float* __restrict__ og)
{
    extern __shared__ float sm[];
    float* ks = sm;            // [256][24]
    float* vs = sm + SEQ * HD; // [256][24]

    const int tid = threadIdx.x;
    const int n   = blockIdx.x;
    const int h   = blockIdx.y;
    const int b   = n >> 8;
    const int wr  = (n >> 4) & 15;
    const int wc  = n & 15;
    const int rowbase = wr * 16;
    const int colbase = wc * 16;

    auto tok = [&](int s) -> int {
        int r = s >> 4, c = s & 15;
        return b * 65536 + (rowbase + r) * 256 + (colbase + c);
    };

    for (int i = tid; i < SEQ * 6; i += 128) {
        int s = i / 6, qd = i - s * 6;
        ((float4*)ks)[i] = *(const float4*)(qkv + (size_t)tok(s) * C3 + h * 72 + qd * 4);
    }
    __syncthreads();
    ull q2[2][12];
    {
        const ull* qa = (const ull*)(ks + tid * HD);
        const ull* qb = (const ull*)(ks + (tid + 128) * HD);
        #pragma unroll
        for (int i = 0; i < 12; i++) { q2[0][i] = qa[i]; q2[1][i] = qb[i]; }
    }
    __syncthreads();

    for (int i = tid; i < SEQ * 6; i += 128) {
        int s = i / 6, qd = i - s * 6;
        size_t base = (size_t)tok(s) * C3 + h * 72;
        ((float4*)ks)[i] = *(const float4*)(qkv + base + 24 + qd * 4);
        ((float4*)vs)[i] = *(const float4*)(qkv + base + 48 + qd * 4);
    }
    __syncthreads();

    const float scale = 0.20412414523193154f; // 1/sqrt(24)

    ull acc[2][12];
    #pragma unroll
    for (int i = 0; i < 12; i++) { acc[0][i] = 0ULL; acc[1][i] = 0ULL; }
    float l0 = 0.f, l1 = 0.f;

    const ulonglong2* krow = (const ulonglong2*)ks;
    const ulonglong2* vrow = (const ulonglong2*)vs;

    #pragma unroll 2
    for (int j = 0; j < SEQ; j++) {
        const ulonglong2* k4 = krow + j * 6;
        ull d0a = 0ULL, d0b = 0ULL, d1a = 0ULL, d1b = 0ULL;
        #pragma unroll
        for (int i = 0; i < 6; i++) {
            ulonglong2 kk = k4[i];
            d0a = ffma2(q2[0][2 * i],     kk.x, d0a);
            d1a = ffma2(q2[1][2 * i],     kk.x, d1a);
            d0b = ffma2(q2[0][2 * i + 1], kk.y, d0b);
            d1b = ffma2(q2[1][2 * i + 1], kk.y, d1b);
        }
        float a, bb, c, d;
        upk2(d0a, a, bb); upk2(d0b, c, d); float s0 = (a + bb + c + d) * scale;
        upk2(d1a, a, bb); upk2(d1b, c, d); float s1 = (a + bb + c + d) * scale;
        float p0 = __expf(s0), p1 = __expf(s1);
        l0 += p0; l1 += p1;
        ull p02 = pk2(p0, p0), p12 = pk2(p1, p1);
        const ulonglong2* v4 = vrow + j * 6;
        #pragma unroll
        for (int i = 0; i < 6; i++) {
            ulonglong2 vv = v4[i];
            acc[0][2 * i]     = ffma2(p02, vv.x, acc[0][2 * i]);
            acc[1][2 * i]     = ffma2(p12, vv.x, acc[1][2 * i]);
            acc[0][2 * i + 1] = ffma2(p02, vv.y, acc[0][2 * i + 1]);
            acc[1][2 * i + 1] = ffma2(p12, vv.y, acc[1][2 * i + 1]);
        }
    }

    #pragma unroll
    for (int rr = 0; rr < 2; rr++) {
        int s = tid + rr * 128;
        float inv = 1.0f / (rr ? l1 : l0);
        float o[24];
        #pragma unroll
        for (int i = 0; i < 12; i++) {
            float lo, hi; upk2(acc[rr][i], lo, hi);
            o[2 * i]     = lo * inv;
            o[2 * i + 1] = hi * inv;
        }
        int r = s >> 4, c = s & 15;
        #pragma unroll
        for (int ky = -1; ky <= 1; ky++) {
            int r2 = r + ky;
            if (r2 < 0 || r2 > 15) continue;
            #pragma unroll
            for (int kx = -1; kx <= 1; kx++) {
                int c2 = c + kx;
                if (c2 < 0 || c2 > 15) continue;
                const float* vr = vs + (r2 * 16 + c2) * HD;
                const float* wrow = pe_w + ((ky + 1) * 3 + (kx + 1)) * CH + h * HD;
                #pragma unroll
                for (int d = 0; d < 24; d++) o[d] += vr[d] * __ldg(wrow + d);
            }
        }
        #pragma unroll
        for (int d = 0; d < 24; d++) o[d] += __ldg(pe_b + h * HD + d);

        float4* dst = (float4*)(og + (size_t)tok(s) * CH + h * HD);
        #pragma unroll
        for (int i = 0; i < 6; i++)
            dst[i] = make_float4(o[4 * i], o[4 * i + 1], o[4 * i + 2], o[4 * i + 3]);
    }
}

// ---------------------------------------------------------------------------
extern "C" void kernel_launch(void* const* d_in, const int* in_sizes, int n_in,
                              void* d_out, int out_size)
{
    const float* x     = (const float*)d_in[0];
    const float* qkv_w = (const float*)d_in[1];
    const float* qkv_b = (const float*)d_in[2];
    const float* pe_w  = (const float*)d_in[3];
    const float* pe_b  = (const float*)d_in[4];
    const float* out_w = (const float*)d_in[5];
    const float* out_b = (const float*)d_in[6];
    float* out = (float*)d_out;

    float* qkv_ptr = nullptr;
    float* o_ptr   = nullptr;
    cudaGetSymbolAddress((void**)&qkv_ptr, g_qkv);
    cudaGetSymbolAddress((void**)&o_ptr,   g_o);

    const int attn_smem = 2 * SEQ * HD * (int)sizeof(float);  // 49152
    cudaFuncSetAttribute(gemm_mma,  cudaFuncAttributeMaxDynamicSharedMemorySize, GEMM_MMA_SMEM);
    cudaFuncSetAttribute(attn_lepe, cudaFuncAttributeMaxDynamicSharedMemorySize, attn_smem);

    // 1) QKV projection (mma.sync bf16 3x-split): 3 N-tiles of 96
    gemm_mma<<<dim3(NTOK / 128, 3), 256, GEMM_MMA_SMEM>>>(x, qkv_w, qkv_b, qkv_ptr, C3, C3);

    // 2) Fused windowed attention + lepe
    attn_lepe<<<dim3(NWIN, NHEADS), 128, attn_smem>>>(qkv_ptr, pe_w, pe_b, o_ptr);

    // 3) Output projection (mma.sync): 1 N-tile of 96
    gemm_mma<<<dim3(NTOK / 128, 1), 256, GEMM_MMA_SMEM>>>(o_ptr, out_w, out_b, out, CH, CH);
}

// round 11
// speedup vs baseline: 1.3600x; 1.2251x over previous
#include <cuda_runtime.h>
#include <cuda_bf16.h>
#include <cstdint>

#define BATCH   2
#define HIMG    256
#define WIMG    256
#define CH      96
#define C3      288
#define WINSZ   16
#define SEQ     256
#define NHEADS  4
#define HD      24
#define NWIN    512
#define NTOK    131072

typedef unsigned long long ull;

__device__ float g_qkv[(size_t)NTOK * C3];
__device__ float g_o  [(size_t)NTOK * CH];

// ---------------- f32x2 helpers (attention) ---------------------------------
__device__ __forceinline__ ull pk2(float lo, float hi) {
    ull r; asm("mov.b64 %0, {%1,%2};" : "=l"(r) : "f"(lo), "f"(hi)); return r;
}
__device__ __forceinline__ void upk2(ull v, float& lo, float& hi) {
    asm("mov.b64 {%0,%1}, %2;" : "=f"(lo), "=f"(hi) : "l"(v));
}
__device__ __forceinline__ ull ffma2(ull a, ull b, ull c) {
    ull d; asm("fma.rn.f32x2 %0, %1, %2, %3;" : "=l"(d) : "l"(a), "l"(b), "l"(c));
    return d;
}

// ---------------- mma helpers ------------------------------------------------
__device__ __forceinline__ uint32_t smem_u32(const void* p) {
    uint32_t a;
    asm("{ .reg .u64 t; cvta.to.shared.u64 t, %1; cvt.u32.u64 %0, t; }" : "=r"(a) : "l"(p));
    return a;
}
__device__ __forceinline__ void ldm_x4(uint32_t addr, uint32_t& r0, uint32_t& r1,
                                       uint32_t& r2, uint32_t& r3) {
    asm volatile("ldmatrix.sync.aligned.m8n8.x4.shared.b16 {%0,%1,%2,%3}, [%4];"
                 : "=r"(r0), "=r"(r1), "=r"(r2), "=r"(r3) : "r"(addr));
}
__device__ __forceinline__ void mma_bf16(float* c, const uint32_t* a, const uint32_t* b) {
    asm volatile(
        "mma.sync.aligned.m16n8k16.row.col.f32.bf16.bf16.f32 "
        "{%0,%1,%2,%3}, {%4,%5,%6,%7}, {%8,%9}, {%0,%1,%2,%3};"
        : "+f"(c[0]), "+f"(c[1]), "+f"(c[2]), "+f"(c[3])
        : "r"(a[0]), "r"(a[1]), "r"(a[2]), "r"(a[3]), "r"(b[0]), "r"(b[1]));
}
// split v into bf16 hi + bf16 lo; return packed later
__device__ __forceinline__ void bf16split(float v, __nv_bfloat16& h, __nv_bfloat16& l) {
    h = __float2bfloat16(v);
    l = __float2bfloat16(v - __bfloat162float(h));
}
__device__ __forceinline__ uint32_t pack_bf2(__nv_bfloat16 a, __nv_bfloat16 b) {
    __nv_bfloat162 t(a, b);
    return *reinterpret_cast<uint32_t*>(&t);
}

// ---------------------------------------------------------------------------
// Tensor-core GEMM (mma.sync bf16, 3-term split): out = A[128,96] @ W[96,96] + b
// Block 256 thr (8 warps, 4x2), warp tile 32x48 (2x6 m16n8k16 tiles).
// Convert phase uses packed STS.64 (bf16x2 pairs) and coalesced W loads —
// R10 showed scattered STS.16 made L1tex (59.6%) the bottleneck, not tensor.
// ---------------------------------------------------------------------------
#define PITCH 104

__global__ __launch_bounds__(256, 2)
void gemm_mma(const float* __restrict__ A, const float* __restrict__ W,
              const float* __restrict__ bias, float* __restrict__ out,
              int wld, int oldd)
{
    extern __shared__ __nv_bfloat16 smbf[];
    __nv_bfloat16* Ahi = smbf;                    // [128][104]
    __nv_bfloat16* Alo = Ahi + 128 * PITCH;
    __nv_bfloat16* Bhi = Alo + 128 * PITCH;       // [96][104]  ([n][k])
    __nv_bfloat16* Blo = Bhi + 96 * PITCH;

    const int tid  = threadIdx.x;
    const int lane = tid & 31;
    const int wid  = tid >> 5;
    const int m0   = blockIdx.x * 128;
    const int n0   = blockIdx.y * 96;

    // ---- convert A tile: 128 rows x 96 floats -> hi/lo bf16 (STS.64 packed) --
    #pragma unroll
    for (int it = 0; it < 12; it++) {
        int idx = tid + it * 256;              // 3072 float4 items
        int m = idx / 24, q = idx - m * 24;    // q = float4 index within row
        float4 v = *(const float4*)(A + (size_t)(m0 + m) * CH + q * 4);
        __nv_bfloat16 h0, h1, h2, h3, l0, l1, l2, l3;
        bf16split(v.x, h0, l0); bf16split(v.y, h1, l1);
        bf16split(v.z, h2, l2); bf16split(v.w, h3, l3);
        uint2 hp = make_uint2(pack_bf2(h0, h1), pack_bf2(h2, h3));
        uint2 lp = make_uint2(pack_bf2(l0, l1), pack_bf2(l2, l3));
        *(uint2*)(Ahi + m * PITCH + q * 4) = hp;
        *(uint2*)(Alo + m * PITCH + q * 4) = lp;
    }
    // ---- convert B tile: W[k][n0+n] -> Bs[n][k] hi/lo, coalesced loads -------
    #pragma unroll
    for (int it = 0; it < 9; it++) {
        int idx = tid + it * 256;              // 2304 items: (n, k-quad)
        int kq = idx / 96, n = idx - kq * 96;  // consecutive tid -> consecutive n
        int kbase = kq * 4;
        float w0 = W[(size_t)(kbase + 0) * wld + n0 + n];
        float w1 = W[(size_t)(kbase + 1) * wld + n0 + n];
        float w2 = W[(size_t)(kbase + 2) * wld + n0 + n];
        float w3 = W[(size_t)(kbase + 3) * wld + n0 + n];
        __nv_bfloat16 h0, h1, h2, h3, l0, l1, l2, l3;
        bf16split(w0, h0, l0); bf16split(w1, h1, l1);
        bf16split(w2, h2, l2); bf16split(w3, h3, l3);
        uint2 hp = make_uint2(pack_bf2(h0, h1), pack_bf2(h2, h3));
        uint2 lp = make_uint2(pack_bf2(l0, l1), pack_bf2(l2, l3));
        *(uint2*)(Bhi + n * PITCH + kbase) = hp;
        *(uint2*)(Blo + n * PITCH + kbase) = lp;
    }
    __syncthreads();

    const int warp_m = wid & 3;    // 0..3 -> m offset 32*warp_m
    const int warp_n = wid >> 2;   // 0..1 -> n offset 48*warp_n

    // ldmatrix thread->address mappings
    const uint32_t a_row  = warp_m * 32 + (lane & 15);
    const uint32_t a_koff = (lane >> 4) * 8;
    uint32_t aHi0 = smem_u32(Ahi + a_row * PITCH + a_koff);
    uint32_t aLo0 = smem_u32(Alo + a_row * PITCH + a_koff);
    const uint32_t b_nrow = warp_n * 48 + (lane & 7) + ((lane >> 4) << 3);
    const uint32_t b_koff = ((lane >> 3) & 1) * 8;
    uint32_t bHi0 = smem_u32(Bhi + b_nrow * PITCH + b_koff);
    uint32_t bLo0 = smem_u32(Blo + b_nrow * PITCH + b_koff);

    float acc[2][6][4];
    #pragma unroll
    for (int i = 0; i < 2; i++)
        #pragma unroll
        for (int j = 0; j < 6; j++)
            #pragma unroll
            for (int q = 0; q < 4; q++) acc[i][j][q] = 0.f;

    #pragma unroll
    for (int c = 0; c < 6; c++) {
        const uint32_t kb = c * 32;   // 16 bf16 = 32 bytes per chunk

        uint32_t ahi[2][4], alo[2][4];
        #pragma unroll
        for (int mt = 0; mt < 2; mt++) {
            ldm_x4(aHi0 + mt * (16 * PITCH * 2) + kb,
                   ahi[mt][0], ahi[mt][1], ahi[mt][2], ahi[mt][3]);
            ldm_x4(aLo0 + mt * (16 * PITCH * 2) + kb,
                   alo[mt][0], alo[mt][1], alo[mt][2], alo[mt][3]);
        }
        uint32_t bhi[6][2], blo[6][2];
        #pragma unroll
        for (int p = 0; p < 3; p++) {
            ldm_x4(bHi0 + p * (16 * PITCH * 2) + kb,
                   bhi[2 * p][0], bhi[2 * p][1], bhi[2 * p + 1][0], bhi[2 * p + 1][1]);
            ldm_x4(bLo0 + p * (16 * PITCH * 2) + kb,
                   blo[2 * p][0], blo[2 * p][1], blo[2 * p + 1][0], blo[2 * p + 1][1]);
        }

        #pragma unroll
        for (int nt = 0; nt < 6; nt++)
            #pragma unroll
            for (int mt = 0; mt < 2; mt++) {
                mma_bf16(acc[mt][nt], ahi[mt], bhi[nt]);   // hi*hi
                mma_bf16(acc[mt][nt], ahi[mt], blo[nt]);   // hi*lo
                mma_bf16(acc[mt][nt], alo[mt], bhi[nt]);   // lo*hi
            }
    }

    // ---- epilogue: bias + float2 stores ----
    #pragma unroll
    for (int nt = 0; nt < 6; nt++) {
        int col = n0 + warp_n * 48 + nt * 8 + (lane & 3) * 2;
        float b0 = __ldg(bias + col), b1 = __ldg(bias + col + 1);
        #pragma unroll
        for (int mt = 0; mt < 2; mt++) {
            int row0 = m0 + warp_m * 32 + mt * 16 + (lane >> 2);
            float2 v0 = make_float2(acc[mt][nt][0] + b0, acc[mt][nt][1] + b1);
            float2 v1 = make_float2(acc[mt][nt][2] + b0, acc[mt][nt][3] + b1);
            *(float2*)(out + (size_t)row0 * oldd + col)       = v0;
            *(float2*)(out + (size_t)(row0 + 8) * oldd + col) = v1;
        }
    }
}

#define GEMM_MMA_SMEM ((2 * 128 * PITCH + 2 * 96 * PITCH) * (int)sizeof(__nv_bfloat16)) // 93184

// ---------------------------------------------------------------------------
// Fused attention + lepe per (window, head). 128 threads, 2 query rows each.
// (unchanged from R10)
// ---------------------------------------------------------------------------
__global__ __launch_bounds__(128, 4)
void attn_lepe(const float* __restrict__ qkv, const float* __restrict__ pe_w,
               const float* __restrict__ pe_b, float* __restrict__ og)
{
    extern __shared__ float sm[];
    float* ks = sm;            // [256][24]
    float* vs = sm + SEQ * HD; // [256][24]

    const int tid = threadIdx.x;
    const int n   = blockIdx.x;
    const int h   = blockIdx.y;
    const int b   = n >> 8;
    const int wr  = (n >> 4) & 15;
    const int wc  = n & 15;
    const int rowbase = wr * 16;
    const int colbase = wc * 16;

    auto tok = [&](int s) -> int {
        int r = s >> 4, c = s & 15;
        return b * 65536 + (rowbase + r) * 256 + (colbase + c);
    };

    for (int i = tid; i < SEQ * 6; i += 128) {
        int s = i / 6, qd = i - s * 6;
        ((float4*)ks)[i] = *(const float4*)(qkv + (size_t)tok(s) * C3 + h * 72 + qd * 4);
    }
    __syncthreads();
    ull q2[2][12];
    {
        const ull* qa = (const ull*)(ks + tid * HD);
        const ull* qb = (const ull*)(ks + (tid + 128) * HD);
        #pragma unroll
        for (int i = 0; i < 12; i++) { q2[0][i] = qa[i]; q2[1][i] = qb[i]; }
    }
    __syncthreads();

    for (int i = tid; i < SEQ * 6; i += 128) {
        int s = i / 6, qd = i - s * 6;
        size_t base = (size_t)tok(s) * C3 + h * 72;
        ((float4*)ks)[i] = *(const float4*)(qkv + base + 24 + qd * 4);
        ((float4*)vs)[i] = *(const float4*)(qkv + base + 48 + qd * 4);
    }
    __syncthreads();

    const float scale = 0.20412414523193154f; // 1/sqrt(24)

    ull acc[2][12];
    #pragma unroll
    for (int i = 0; i < 12; i++) { acc[0][i] = 0ULL; acc[1][i] = 0ULL; }
    float l0 = 0.f, l1 = 0.f;

    const ulonglong2* krow = (const ulonglong2*)ks;
    const ulonglong2* vrow = (const ulonglong2*)vs;

    #pragma unroll 2
    for (int j = 0; j < SEQ; j++) {
        const ulonglong2* k4 = krow + j * 6;
        ull d0a = 0ULL, d0b = 0ULL, d1a = 0ULL, d1b = 0ULL;
        #pragma unroll
        for (int i = 0; i < 6; i++) {
            ulonglong2 kk = k4[i];
            d0a = ffma2(q2[0][2 * i],     kk.x, d0a);
            d1a = ffma2(q2[1][2 * i],     kk.x, d1a);
            d0b = ffma2(q2[0][2 * i + 1], kk.y, d0b);
            d1b = ffma2(q2[1][2 * i + 1], kk.y, d1b);
        }
        float a, bb, c, d;
        upk2(d0a, a, bb); upk2(d0b, c, d); float s0 = (a + bb + c + d) * scale;
        upk2(d1a, a, bb); upk2(d1b, c, d); float s1 = (a + bb + c + d) * scale;
        float p0 = __expf(s0), p1 = __expf(s1);
        l0 += p0; l1 += p1;
        ull p02 = pk2(p0, p0), p12 = pk2(p1, p1);
        const ulonglong2* v4 = vrow + j * 6;
        #pragma unroll
        for (int i = 0; i < 6; i++) {
            ulonglong2 vv = v4[i];
            acc[0][2 * i]     = ffma2(p02, vv.x, acc[0][2 * i]);
            acc[1][2 * i]     = ffma2(p12, vv.x, acc[1][2 * i]);
            acc[0][2 * i + 1] = ffma2(p02, vv.y, acc[0][2 * i + 1]);
            acc[1][2 * i + 1] = ffma2(p12, vv.y, acc[1][2 * i + 1]);
        }
    }

    #pragma unroll
    for (int rr = 0; rr < 2; rr++) {
        int s = tid + rr * 128;
        float inv = 1.0f / (rr ? l1 : l0);
        float o[24];
        #pragma unroll
        for (int i = 0; i < 12; i++) {
            float lo, hi; upk2(acc[rr][i], lo, hi);
            o[2 * i]     = lo * inv;
            o[2 * i + 1] = hi * inv;
        }
        int r = s >> 4, c = s & 15;
        #pragma unroll
        for (int ky = -1; ky <= 1; ky++) {
            int r2 = r + ky;
            if (r2 < 0 || r2 > 15) continue;
            #pragma unroll
            for (int kx = -1; kx <= 1; kx++) {
                int c2 = c + kx;
                if (c2 < 0 || c2 > 15) continue;
                const float* vr = vs + (r2 * 16 + c2) * HD;
                const float* wrow = pe_w + ((ky + 1) * 3 + (kx + 1)) * CH + h * HD;
                #pragma unroll
                for (int d = 0; d < 24; d++) o[d] += vr[d] * __ldg(wrow + d);
            }
        }
        #pragma unroll
        for (int d = 0; d < 24; d++) o[d] += __ldg(pe_b + h * HD + d);

        float4* dst = (float4*)(og + (size_t)tok(s) * CH + h * HD);
        #pragma unroll
        for (int i = 0; i < 6; i++)
            dst[i] = make_float4(o[4 * i], o[4 * i + 1], o[4 * i + 2], o[4 * i + 3]);
    }
}

// ---------------------------------------------------------------------------
extern "C" void kernel_launch(void* const* d_in, const int* in_sizes, int n_in,
                              void* d_out, int out_size)
{
    const float* x     = (const float*)d_in[0];
    const float* qkv_w = (const float*)d_in[1];
    const float* qkv_b = (const float*)d_in[2];
    const float* pe_w  = (const float*)d_in[3];
    const float* pe_b  = (const float*)d_in[4];
    const float* out_w = (const float*)d_in[5];
    const float* out_b = (const float*)d_in[6];
    float* out = (float*)d_out;

    float* qkv_ptr = nullptr;
    float* o_ptr   = nullptr;
    cudaGetSymbolAddress((void**)&qkv_ptr, g_qkv);
    cudaGetSymbolAddress((void**)&o_ptr,   g_o);

    const int attn_smem = 2 * SEQ * HD * (int)sizeof(float);  // 49152
    cudaFuncSetAttribute(gemm_mma,  cudaFuncAttributeMaxDynamicSharedMemorySize, GEMM_MMA_SMEM);
    cudaFuncSetAttribute(attn_lepe, cudaFuncAttributeMaxDynamicSharedMemorySize, attn_smem);

    // 1) QKV projection (mma.sync bf16 3x-split): 3 N-tiles of 96
    gemm_mma<<<dim3(NTOK / 128, 3), 256, GEMM_MMA_SMEM>>>(x, qkv_w, qkv_b, qkv_ptr, C3, C3);

    // 2) Fused windowed attention + lepe
    attn_lepe<<<dim3(NWIN, NHEADS), 128, attn_smem>>>(qkv_ptr, pe_w, pe_b, o_ptr);

    // 3) Output projection (mma.sync): 1 N-tile of 96
    gemm_mma<<<dim3(NTOK / 128, 1), 256, GEMM_MMA_SMEM>>>(o_ptr, out_w, out_b, out, CH, CH);
}

// round 12
// speedup vs baseline: 2.3979x; 1.7632x over previous
#include <cuda_runtime.h>
#include <cuda_bf16.h>
#include <cstdint>

#define BATCH   2
#define HIMG    256
#define WIMG    256
#define CH      96
#define C3      288
#define WINSZ   16
#define SEQ     256
#define NHEADS  4
#define HD      24
#define NWIN    512
#define NTOK    131072

typedef unsigned long long ull;

__device__ float g_qkv[(size_t)NTOK * C3];
__device__ float g_o  [(size_t)NTOK * CH];

// ---------------- mma helpers ------------------------------------------------
__device__ __forceinline__ uint32_t smem_u32(const void* p) {
    uint32_t a;
    asm("{ .reg .u64 t; cvta.to.shared.u64 t, %1; cvt.u32.u64 %0, t; }" : "=r"(a) : "l"(p));
    return a;
}
__device__ __forceinline__ void ldm_x4(uint32_t addr, uint32_t& r0, uint32_t& r1,
                                       uint32_t& r2, uint32_t& r3) {
    asm volatile("ldmatrix.sync.aligned.m8n8.x4.shared.b16 {%0,%1,%2,%3}, [%4];"
                 : "=r"(r0), "=r"(r1), "=r"(r2), "=r"(r3) : "r"(addr));
}
__device__ __forceinline__ void ldm_x4_trans(uint32_t addr, uint32_t& r0, uint32_t& r1,
                                             uint32_t& r2, uint32_t& r3) {
    asm volatile("ldmatrix.sync.aligned.m8n8.x4.trans.shared.b16 {%0,%1,%2,%3}, [%4];"
                 : "=r"(r0), "=r"(r1), "=r"(r2), "=r"(r3) : "r"(addr));
}
__device__ __forceinline__ void mma_bf16(float* c, const uint32_t* a, const uint32_t* b) {
    asm volatile(
        "mma.sync.aligned.m16n8k16.row.col.f32.bf16.bf16.f32 "
        "{%0,%1,%2,%3}, {%4,%5,%6,%7}, {%8,%9}, {%0,%1,%2,%3};"
        : "+f"(c[0]), "+f"(c[1]), "+f"(c[2]), "+f"(c[3])
        : "r"(a[0]), "r"(a[1]), "r"(a[2]), "r"(a[3]), "r"(b[0]), "r"(b[1]));
}
__device__ __forceinline__ void bf16split(float v, __nv_bfloat16& h, __nv_bfloat16& l) {
    h = __float2bfloat16(v);
    l = __float2bfloat16(v - __bfloat162float(h));
}
__device__ __forceinline__ uint32_t pack_bf2(__nv_bfloat16 a, __nv_bfloat16 b) {
    __nv_bfloat162 t(a, b);
    return *reinterpret_cast<uint32_t*>(&t);
}
__device__ __forceinline__ uint32_t pack_bf2f(float a, float b) {
    return pack_bf2(__float2bfloat16(a), __float2bfloat16(b));
}

// ---------------------------------------------------------------------------
// Tensor-core GEMM (mma.sync bf16, 3-term split) — unchanged from R11 (WIN).
// ---------------------------------------------------------------------------
#define PITCH 104

__global__ __launch_bounds__(256, 2)
void gemm_mma(const float* __restrict__ A, const float* __restrict__ W,
              const float* __restrict__ bias, float* __restrict__ out,
              int wld, int oldd)
{
    extern __shared__ __nv_bfloat16 smbf[];
    __nv_bfloat16* Ahi = smbf;                    // [128][104]
    __nv_bfloat16* Alo = Ahi + 128 * PITCH;
    __nv_bfloat16* Bhi = Alo + 128 * PITCH;       // [96][104]  ([n][k])
    __nv_bfloat16* Blo = Bhi + 96 * PITCH;

    const int tid  = threadIdx.x;
    const int lane = tid & 31;
    const int wid  = tid >> 5;
    const int m0   = blockIdx.x * 128;
    const int n0   = blockIdx.y * 96;

    #pragma unroll
    for (int it = 0; it < 12; it++) {
        int idx = tid + it * 256;
        int m = idx / 24, q = idx - m * 24;
        float4 v = *(const float4*)(A + (size_t)(m0 + m) * CH + q * 4);
        __nv_bfloat16 h0, h1, h2, h3, l0, l1, l2, l3;
        bf16split(v.x, h0, l0); bf16split(v.y, h1, l1);
        bf16split(v.z, h2, l2); bf16split(v.w, h3, l3);
        uint2 hp = make_uint2(pack_bf2(h0, h1), pack_bf2(h2, h3));
        uint2 lp = make_uint2(pack_bf2(l0, l1), pack_bf2(l2, l3));
        *(uint2*)(Ahi + m * PITCH + q * 4) = hp;
        *(uint2*)(Alo + m * PITCH + q * 4) = lp;
    }
    #pragma unroll
    for (int it = 0; it < 9; it++) {
        int idx = tid + it * 256;
        int kq = idx / 96, n = idx - kq * 96;
        int kbase = kq * 4;
        float w0 = W[(size_t)(kbase + 0) * wld + n0 + n];
        float w1 = W[(size_t)(kbase + 1) * wld + n0 + n];
        float w2 = W[(size_t)(kbase + 2) * wld + n0 + n];
        float w3 = W[(size_t)(kbase + 3) * wld + n0 + n];
        __nv_bfloat16 h0, h1, h2, h3, l0, l1, l2, l3;
        bf16split(w0, h0, l0); bf16split(w1, h1, l1);
        bf16split(w2, h2, l2); bf16split(w3, h3, l3);
        uint2 hp = make_uint2(pack_bf2(h0, h1), pack_bf2(h2, h3));
        uint2 lp = make_uint2(pack_bf2(l0, l1), pack_bf2(l2, l3));
        *(uint2*)(Bhi + n * PITCH + kbase) = hp;
        *(uint2*)(Blo + n * PITCH + kbase) = lp;
    }
    __syncthreads();

    const int warp_m = wid & 3;
    const int warp_n = wid >> 2;

    const uint32_t a_row  = warp_m * 32 + (lane & 15);
    const uint32_t a_koff = (lane >> 4) * 8;
    uint32_t aHi0 = smem_u32(Ahi + a_row * PITCH + a_koff);
    uint32_t aLo0 = smem_u32(Alo + a_row * PITCH + a_koff);
    const uint32_t b_nrow = warp_n * 48 + (lane & 7) + ((lane >> 4) << 3);
    const uint32_t b_koff = ((lane >> 3) & 1) * 8;
    uint32_t bHi0 = smem_u32(Bhi + b_nrow * PITCH + b_koff);
    uint32_t bLo0 = smem_u32(Blo + b_nrow * PITCH + b_koff);

    float acc[2][6][4];
    #pragma unroll
    for (int i = 0; i < 2; i++)
        #pragma unroll
        for (int j = 0; j < 6; j++)
            #pragma unroll
            for (int q = 0; q < 4; q++) acc[i][j][q] = 0.f;

    #pragma unroll
    for (int c = 0; c < 6; c++) {
        const uint32_t kb = c * 32;

        uint32_t ahi[2][4], alo[2][4];
        #pragma unroll
        for (int mt = 0; mt < 2; mt++) {
            ldm_x4(aHi0 + mt * (16 * PITCH * 2) + kb,
                   ahi[mt][0], ahi[mt][1], ahi[mt][2], ahi[mt][3]);
            ldm_x4(aLo0 + mt * (16 * PITCH * 2) + kb,
                   alo[mt][0], alo[mt][1], alo[mt][2], alo[mt][3]);
        }
        uint32_t bhi[6][2], blo[6][2];
        #pragma unroll
        for (int p = 0; p < 3; p++) {
            ldm_x4(bHi0 + p * (16 * PITCH * 2) + kb,
                   bhi[2 * p][0], bhi[2 * p][1], bhi[2 * p + 1][0], bhi[2 * p + 1][1]);
            ldm_x4(bLo0 + p * (16 * PITCH * 2) + kb,
                   blo[2 * p][0], blo[2 * p][1], blo[2 * p + 1][0], blo[2 * p + 1][1]);
        }

        #pragma unroll
        for (int nt = 0; nt < 6; nt++)
            #pragma unroll
            for (int mt = 0; mt < 2; mt++) {
                mma_bf16(acc[mt][nt], ahi[mt], bhi[nt]);
                mma_bf16(acc[mt][nt], ahi[mt], blo[nt]);
                mma_bf16(acc[mt][nt], alo[mt], bhi[nt]);
            }
    }

    #pragma unroll
    for (int nt = 0; nt < 6; nt++) {
        int col = n0 + warp_n * 48 + nt * 8 + (lane & 3) * 2;
        float b0 = __ldg(bias + col), b1 = __ldg(bias + col + 1);
        #pragma unroll
        for (int mt = 0; mt < 2; mt++) {
            int row0 = m0 + warp_m * 32 + mt * 16 + (lane >> 2);
            float2 v0 = make_float2(acc[mt][nt][0] + b0, acc[mt][nt][1] + b1);
            float2 v1 = make_float2(acc[mt][nt][2] + b0, acc[mt][nt][3] + b1);
            *(float2*)(out + (size_t)row0 * oldd + col)       = v0;
            *(float2*)(out + (size_t)(row0 + 8) * oldd + col) = v1;
        }
    }
}

#define GEMM_MMA_SMEM ((2 * 128 * PITCH + 2 * 96 * PITCH) * (int)sizeof(__nv_bfloat16)) // 93184

// ---------------------------------------------------------------------------
// Tensor-core fused attention + lepe per (window, head).
// 256 threads / 8 warps; warp w owns q-rows [32w, 32w+32) (2 m16-tiles).
// Keys in 16 blocks of 16. QK^T plain bf16 (logits tiny -> err ~1.6e-4);
// softmax fp32 on C-fragments; PV with 2-way bf16 split on both P and V.
// V stored [key][d] (coalesced), B-fragments via ldmatrix.trans.
// Pitch 40 bf16 (80B): ldmatrix rows mod 128B all distinct (conflict-free).
// ---------------------------------------------------------------------------
#define AP 40                         // bf16 pitch for Q/K/V smem
#define ASM_Q  0
#define ASM_K  (256 * AP)             // bf16 elements
#define ASM_VH (512 * AP)
#define ASM_VL (768 * AP)
#define ATT_SMEM (1024 * AP * 2)      // 81920 bytes

__global__ __launch_bounds__(256, 2)
void attn_mma(const float* __restrict__ qkv, const float* __restrict__ pe_w,
              const float* __restrict__ pe_b, float* __restrict__ og)
{
    extern __shared__ __nv_bfloat16 asm_bf[];
    __nv_bfloat16* Qs = asm_bf + ASM_Q;    // [256][40]
    __nv_bfloat16* Ks = asm_bf + ASM_K;    // [256][40]
    __nv_bfloat16* Vh = asm_bf + ASM_VH;   // [256][40]
    __nv_bfloat16* Vl = asm_bf + ASM_VL;   // [256][40]

    const int tid  = threadIdx.x;
    const int lane = tid & 31;
    const int warp = tid >> 5;
    const int n    = blockIdx.x;
    const int h    = blockIdx.y;
    const int b    = n >> 8;
    const int rowbase = ((n >> 4) & 15) * 16;
    const int colbase = (n & 15) * 16;

    auto tok = [&](int s) -> int {
        int r = s >> 4, c = s & 15;
        return b * 65536 + (rowbase + r) * 256 + (colbase + c);
    };

    // ---- zero smem (covers pad cols 24..39) ----
    #pragma unroll
    for (int i = tid; i < ATT_SMEM / 16; i += 256)
        ((uint4*)asm_bf)[i] = make_uint4(0, 0, 0, 0);
    __syncthreads();

    const float scale = 0.20412414523193154f; // 1/sqrt(24), folded into Q

    // ---- load Q (prescaled), K, V(hi/lo split); packed STS.64 ----
    #pragma unroll
    for (int it = 0; it < 6; it++) {
        int idx = tid + it * 256;          // 1536 float4 items
        int s = idx / 6, qd = idx - s * 6;
        size_t base = (size_t)tok(s) * C3 + h * 72;
        float4 q = *(const float4*)(qkv + base + qd * 4);
        float4 k = *(const float4*)(qkv + base + 24 + qd * 4);
        float4 v = *(const float4*)(qkv + base + 48 + qd * 4);
        uint2 qp = make_uint2(pack_bf2f(q.x * scale, q.y * scale),
                              pack_bf2f(q.z * scale, q.w * scale));
        uint2 kp = make_uint2(pack_bf2f(k.x, k.y), pack_bf2f(k.z, k.w));
        __nv_bfloat16 h0, h1, h2, h3, l0, l1, l2, l3;
        bf16split(v.x, h0, l0); bf16split(v.y, h1, l1);
        bf16split(v.z, h2, l2); bf16split(v.w, h3, l3);
        uint2 vhp = make_uint2(pack_bf2(h0, h1), pack_bf2(h2, h3));
        uint2 vlp = make_uint2(pack_bf2(l0, l1), pack_bf2(l2, l3));
        *(uint2*)(Qs + s * AP + qd * 4) = qp;
        *(uint2*)(Ks + s * AP + qd * 4) = kp;
        *(uint2*)(Vh + s * AP + qd * 4) = vhp;
        *(uint2*)(Vl + s * AP + qd * 4) = vlp;
    }
    __syncthreads();

    // ---- Q fragments (held all loop) ----
    uint32_t qa[2][2][4];   // [mt][kchunk][4]
    #pragma unroll
    for (int mt = 0; mt < 2; mt++)
        #pragma unroll
        for (int kc = 0; kc < 2; kc++) {
            uint32_t addr = smem_u32(Qs + (warp * 32 + mt * 16 + (lane & 15)) * AP
                                        + kc * 16 + (lane >> 4) * 8);
            ldm_x4(addr, qa[mt][kc][0], qa[mt][kc][1], qa[mt][kc][2], qa[mt][kc][3]);
        }

    float O[2][3][4];
    #pragma unroll
    for (int mt = 0; mt < 2; mt++)
        #pragma unroll
        for (int dt = 0; dt < 3; dt++)
            #pragma unroll
            for (int q = 0; q < 4; q++) O[mt][dt][q] = 0.f;
    float lsum[2][2] = {{0.f, 0.f}, {0.f, 0.f}};

    // per-lane static offsets
    const uint32_t k_row8  = (lane & 7) + ((lane >> 4) << 3);   // QK B rows
    const uint32_t k_koff  = ((lane >> 3) & 1) * 8;
    const uint32_t v_row8  = (lane & 7) + ((lane >> 3) & 1) * 8; // V trans rows
    const uint32_t v_dcol  = ((lane >> 4) & 1) * 8;

    for (int kb = 0; kb < 16; kb++) {
        // K fragments: [ntile][kchunk][2]
        uint32_t kf[2][2][2];
        #pragma unroll
        for (int kc = 0; kc < 2; kc++) {
            uint32_t addr = smem_u32(Ks + (kb * 16 + k_row8) * AP + kc * 16 + k_koff);
            ldm_x4(addr, kf[0][kc][0], kf[0][kc][1], kf[1][kc][0], kf[1][kc][1]);
        }

        // S = Q K^T
        float S[2][2][4];
        #pragma unroll
        for (int mt = 0; mt < 2; mt++)
            #pragma unroll
            for (int nt = 0; nt < 2; nt++) {
                #pragma unroll
                for (int q = 0; q < 4; q++) S[mt][nt][q] = 0.f;
                mma_bf16(S[mt][nt], qa[mt][0], kf[nt][0]);
                mma_bf16(S[mt][nt], qa[mt][1], kf[nt][1]);
            }

        // softmax numerator + row sums + P fragments (hi/lo split)
        uint32_t ph[2][4], pl[2][4];
        #pragma unroll
        for (int mt = 0; mt < 2; mt++) {
            float p[2][4];
            #pragma unroll
            for (int nt = 0; nt < 2; nt++) {
                #pragma unroll
                for (int q = 0; q < 4; q++) p[nt][q] = __expf(S[mt][nt][q]);
                lsum[mt][0] += p[nt][0] + p[nt][1];
                lsum[mt][1] += p[nt][2] + p[nt][3];
            }
            __nv_bfloat16 hh[8], ll[8];
            #pragma unroll
            for (int nt = 0; nt < 2; nt++)
                #pragma unroll
                for (int q = 0; q < 4; q++)
                    bf16split(p[nt][q], hh[nt * 4 + q], ll[nt * 4 + q]);
            ph[mt][0] = pack_bf2(hh[0], hh[1]); ph[mt][1] = pack_bf2(hh[2], hh[3]);
            ph[mt][2] = pack_bf2(hh[4], hh[5]); ph[mt][3] = pack_bf2(hh[6], hh[7]);
            pl[mt][0] = pack_bf2(ll[0], ll[1]); pl[mt][1] = pack_bf2(ll[2], ll[3]);
            pl[mt][2] = pack_bf2(ll[4], ll[5]); pl[mt][3] = pack_bf2(ll[6], ll[7]);
        }

        // V fragments via ldmatrix.trans: [dtile][2]
        uint32_t vhf[3][2], vlf[3][2], d0, d1;
        {
            uint32_t ah = smem_u32(Vh + (kb * 16 + v_row8) * AP + v_dcol);
            uint32_t al = smem_u32(Vl + (kb * 16 + v_row8) * AP + v_dcol);
            ldm_x4_trans(ah, vhf[0][0], vhf[0][1], vhf[1][0], vhf[1][1]);
            ldm_x4_trans(al, vlf[0][0], vlf[0][1], vlf[1][0], vlf[1][1]);
            uint32_t ah2 = smem_u32(Vh + (kb * 16 + v_row8) * AP + 16 + v_dcol);
            uint32_t al2 = smem_u32(Vl + (kb * 16 + v_row8) * AP + 16 + v_dcol);
            ldm_x4_trans(ah2, vhf[2][0], vhf[2][1], d0, d1);   // d 24-31 pad ignored
            ldm_x4_trans(al2, vlf[2][0], vlf[2][1], d0, d1);
        }

        // O += P V  (ph*vh + ph*vl + pl*vh)
        #pragma unroll
        for (int mt = 0; mt < 2; mt++)
            #pragma unroll
            for (int dt = 0; dt < 3; dt++) {
                mma_bf16(O[mt][dt], ph[mt], vhf[dt]);
                mma_bf16(O[mt][dt], ph[mt], vlf[dt]);
                mma_bf16(O[mt][dt], pl[mt], vhf[dt]);
            }
    }

    // ---- finalize row sums (lanes 4g..4g+3 share rows) ----
    float inv[2][2];
    #pragma unroll
    for (int mt = 0; mt < 2; mt++)
        #pragma unroll
        for (int r = 0; r < 2; r++) {
            float v = lsum[mt][r];
            v += __shfl_xor_sync(0xffffffff, v, 1);
            v += __shfl_xor_sync(0xffffffff, v, 2);
            inv[mt][r] = 1.0f / v;
        }

    // ---- write normalized O to smem (overlays dead Q/K region) ----
    __syncthreads();
    float* osm = (float*)asm_bf;    // [256][24]
    #pragma unroll
    for (int mt = 0; mt < 2; mt++) {
        int row = warp * 32 + mt * 16 + (lane >> 2);
        #pragma unroll
        for (int dt = 0; dt < 3; dt++) {
            int col = dt * 8 + (lane & 3) * 2;
            *(float2*)(osm + row * 24 + col) =
                make_float2(O[mt][dt][0] * inv[mt][0], O[mt][dt][1] * inv[mt][0]);
            *(float2*)(osm + (row + 8) * 24 + col) =
                make_float2(O[mt][dt][2] * inv[mt][1], O[mt][dt][3] * inv[mt][1]);
        }
    }
    __syncthreads();

    // ---- lepe (3x3 depthwise on V) + store, one token per thread ----
    {
        int s = tid;
        float o[24];
        #pragma unroll
        for (int i = 0; i < 6; i++) {
            float4 v4 = *(float4*)(osm + s * 24 + i * 4);
            o[4 * i] = v4.x; o[4 * i + 1] = v4.y; o[4 * i + 2] = v4.z; o[4 * i + 3] = v4.w;
        }
        int r = s >> 4, c = s & 15;
        #pragma unroll
        for (int ky = -1; ky <= 1; ky++) {
            int r2 = r + ky;
            if (r2 < 0 || r2 > 15) continue;
            #pragma unroll
            for (int kx = -1; kx <= 1; kx++) {
                int c2 = c + kx;
                if (c2 < 0 || c2 > 15) continue;
                const uint32_t* vh2 = (const uint32_t*)(Vh + (r2 * 16 + c2) * AP);
                const uint32_t* vl2 = (const uint32_t*)(Vl + (r2 * 16 + c2) * AP);
                const float* wrow = pe_w + ((ky + 1) * 3 + (kx + 1)) * CH + h * HD;
                #pragma unroll
                for (int i = 0; i < 12; i++) {
                    __nv_bfloat162 hb = *(const __nv_bfloat162*)&vh2[i];
                    __nv_bfloat162 lb = *(const __nv_bfloat162*)&vl2[i];
                    float2 hf = __bfloat1622float2(hb);
                    float2 lf = __bfloat1622float2(lb);
                    o[2 * i]     += (hf.x + lf.x) * __ldg(wrow + 2 * i);
                    o[2 * i + 1] += (hf.y + lf.y) * __ldg(wrow + 2 * i + 1);
                }
            }
        }
        #pragma unroll
        for (int d = 0; d < 24; d++) o[d] += __ldg(pe_b + h * HD + d);

        float4* dst = (float4*)(og + (size_t)tok(s) * CH + h * HD);
        #pragma unroll
        for (int i = 0; i < 6; i++)
            dst[i] = make_float4(o[4 * i], o[4 * i + 1], o[4 * i + 2], o[4 * i + 3]);
    }
}

// ---------------------------------------------------------------------------
extern "C" void kernel_launch(void* const* d_in, const int* in_sizes, int n_in,
                              void* d_out, int out_size)
{
    const float* x     = (const float*)d_in[0];
    const float* qkv_w = (const float*)d_in[1];
    const float* qkv_b = (const float*)d_in[2];
    const float* pe_w  = (const float*)d_in[3];
    const float* pe_b  = (const float*)d_in[4];
    const float* out_w = (const float*)d_in[5];
    const float* out_b = (const float*)d_in[6];
    float* out = (float*)d_out;

    float* qkv_ptr = nullptr;
    float* o_ptr   = nullptr;
    cudaGetSymbolAddress((void**)&qkv_ptr, g_qkv);
    cudaGetSymbolAddress((void**)&o_ptr,   g_o);

    cudaFuncSetAttribute(gemm_mma, cudaFuncAttributeMaxDynamicSharedMemorySize, GEMM_MMA_SMEM);
    cudaFuncSetAttribute(attn_mma, cudaFuncAttributeMaxDynamicSharedMemorySize, ATT_SMEM);

    // 1) QKV projection (mma.sync bf16 3x-split): 3 N-tiles of 96
    gemm_mma<<<dim3(NTOK / 128, 3), 256, GEMM_MMA_SMEM>>>(x, qkv_w, qkv_b, qkv_ptr, C3, C3);

    // 2) Fused windowed attention + lepe (mma.sync)
    attn_mma<<<dim3(NWIN, NHEADS), 256, ATT_SMEM>>>(qkv_ptr, pe_w, pe_b, o_ptr);

    // 3) Output projection (mma.sync): 1 N-tile of 96
    gemm_mma<<<dim3(NTOK / 128, 1), 256, GEMM_MMA_SMEM>>>(o_ptr, out_w, out_b, out, CH, CH);
}

// round 13
// speedup vs baseline: 2.6125x; 1.0895x over previous
#include <cuda_runtime.h>
#include <cuda_bf16.h>
#include <cstdint>

#define BATCH   2
#define HIMG    256
#define WIMG    256
#define CH      96
#define C3      288
#define WINSZ   16
#define SEQ     256
#define NHEADS  4
#define HD      24
#define NWIN    512
#define NTOK    131072

typedef unsigned long long ull;

__device__ float g_qkv[(size_t)NTOK * C3];
__device__ float g_o  [(size_t)NTOK * CH];

// ---------------- mma helpers ------------------------------------------------
__device__ __forceinline__ uint32_t smem_u32(const void* p) {
    uint32_t a;
    asm("{ .reg .u64 t; cvta.to.shared.u64 t, %1; cvt.u32.u64 %0, t; }" : "=r"(a) : "l"(p));
    return a;
}
__device__ __forceinline__ void ldm_x4(uint32_t addr, uint32_t& r0, uint32_t& r1,
                                       uint32_t& r2, uint32_t& r3) {
    asm volatile("ldmatrix.sync.aligned.m8n8.x4.shared.b16 {%0,%1,%2,%3}, [%4];"
                 : "=r"(r0), "=r"(r1), "=r"(r2), "=r"(r3) : "r"(addr));
}
__device__ __forceinline__ void ldm_x4_trans(uint32_t addr, uint32_t& r0, uint32_t& r1,
                                             uint32_t& r2, uint32_t& r3) {
    asm volatile("ldmatrix.sync.aligned.m8n8.x4.trans.shared.b16 {%0,%1,%2,%3}, [%4];"
                 : "=r"(r0), "=r"(r1), "=r"(r2), "=r"(r3) : "r"(addr));
}
__device__ __forceinline__ void ldm_x2_trans(uint32_t addr, uint32_t& r0, uint32_t& r1) {
    asm volatile("ldmatrix.sync.aligned.m8n8.x2.trans.shared.b16 {%0,%1}, [%2];"
                 : "=r"(r0), "=r"(r1) : "r"(addr));
}
__device__ __forceinline__ void mma_bf16(float* c, const uint32_t* a, const uint32_t* b) {
    asm volatile(
        "mma.sync.aligned.m16n8k16.row.col.f32.bf16.bf16.f32 "
        "{%0,%1,%2,%3}, {%4,%5,%6,%7}, {%8,%9}, {%0,%1,%2,%3};"
        : "+f"(c[0]), "+f"(c[1]), "+f"(c[2]), "+f"(c[3])
        : "r"(a[0]), "r"(a[1]), "r"(a[2]), "r"(a[3]), "r"(b[0]), "r"(b[1]));
}
__device__ __forceinline__ void bf16split(float v, __nv_bfloat16& h, __nv_bfloat16& l) {
    h = __float2bfloat16(v);
    l = __float2bfloat16(v - __bfloat162float(h));
}
__device__ __forceinline__ uint32_t pack_bf2(__nv_bfloat16 a, __nv_bfloat16 b) {
    __nv_bfloat162 t(a, b);
    return *reinterpret_cast<uint32_t*>(&t);
}
// packed bf16x2 {lo, hi} in ONE instruction (first src -> high half)
__device__ __forceinline__ uint32_t cvt_bf16x2(float hi, float lo) {
    uint32_t r; asm("cvt.rn.bf16x2.f32 %0, %1, %2;" : "=r"(r) : "f"(hi), "f"(lo)); return r;
}
__device__ __forceinline__ float ex2f(float x) {
    float y; asm("ex2.approx.f32 %0, %1;" : "=f"(y) : "f"(x)); return y;
}

// ---------------------------------------------------------------------------
// Tensor-core GEMM (mma.sync bf16, 3-term split) — unchanged from R12 (WIN).
// ---------------------------------------------------------------------------
#define PITCH 104

__global__ __launch_bounds__(256, 2)
void gemm_mma(const float* __restrict__ A, const float* __restrict__ W,
              const float* __restrict__ bias, float* __restrict__ out,
              int wld, int oldd)
{
    extern __shared__ __nv_bfloat16 smbf[];
    __nv_bfloat16* Ahi = smbf;
    __nv_bfloat16* Alo = Ahi + 128 * PITCH;
    __nv_bfloat16* Bhi = Alo + 128 * PITCH;
    __nv_bfloat16* Blo = Bhi + 96 * PITCH;

    const int tid  = threadIdx.x;
    const int lane = tid & 31;
    const int wid  = tid >> 5;
    const int m0   = blockIdx.x * 128;
    const int n0   = blockIdx.y * 96;

    #pragma unroll
    for (int it = 0; it < 12; it++) {
        int idx = tid + it * 256;
        int m = idx / 24, q = idx - m * 24;
        float4 v = *(const float4*)(A + (size_t)(m0 + m) * CH + q * 4);
        __nv_bfloat16 h0, h1, h2, h3, l0, l1, l2, l3;
        bf16split(v.x, h0, l0); bf16split(v.y, h1, l1);
        bf16split(v.z, h2, l2); bf16split(v.w, h3, l3);
        uint2 hp = make_uint2(pack_bf2(h0, h1), pack_bf2(h2, h3));
        uint2 lp = make_uint2(pack_bf2(l0, l1), pack_bf2(l2, l3));
        *(uint2*)(Ahi + m * PITCH + q * 4) = hp;
        *(uint2*)(Alo + m * PITCH + q * 4) = lp;
    }
    #pragma unroll
    for (int it = 0; it < 9; it++) {
        int idx = tid + it * 256;
        int kq = idx / 96, n = idx - kq * 96;
        int kbase = kq * 4;
        float w0 = W[(size_t)(kbase + 0) * wld + n0 + n];
        float w1 = W[(size_t)(kbase + 1) * wld + n0 + n];
        float w2 = W[(size_t)(kbase + 2) * wld + n0 + n];
        float w3 = W[(size_t)(kbase + 3) * wld + n0 + n];
        __nv_bfloat16 h0, h1, h2, h3, l0, l1, l2, l3;
        bf16split(w0, h0, l0); bf16split(w1, h1, l1);
        bf16split(w2, h2, l2); bf16split(w3, h3, l3);
        uint2 hp = make_uint2(pack_bf2(h0, h1), pack_bf2(h2, h3));
        uint2 lp = make_uint2(pack_bf2(l0, l1), pack_bf2(l2, l3));
        *(uint2*)(Bhi + n * PITCH + kbase) = hp;
        *(uint2*)(Blo + n * PITCH + kbase) = lp;
    }
    __syncthreads();

    const int warp_m = wid & 3;
    const int warp_n = wid >> 2;

    const uint32_t a_row  = warp_m * 32 + (lane & 15);
    const uint32_t a_koff = (lane >> 4) * 8;
    uint32_t aHi0 = smem_u32(Ahi + a_row * PITCH + a_koff);
    uint32_t aLo0 = smem_u32(Alo + a_row * PITCH + a_koff);
    const uint32_t b_nrow = warp_n * 48 + (lane & 7) + ((lane >> 4) << 3);
    const uint32_t b_koff = ((lane >> 3) & 1) * 8;
    uint32_t bHi0 = smem_u32(Bhi + b_nrow * PITCH + b_koff);
    uint32_t bLo0 = smem_u32(Blo + b_nrow * PITCH + b_koff);

    float acc[2][6][4];
    #pragma unroll
    for (int i = 0; i < 2; i++)
        #pragma unroll
        for (int j = 0; j < 6; j++)
            #pragma unroll
            for (int q = 0; q < 4; q++) acc[i][j][q] = 0.f;

    #pragma unroll
    for (int c = 0; c < 6; c++) {
        const uint32_t kb = c * 32;

        uint32_t ahi[2][4], alo[2][4];
        #pragma unroll
        for (int mt = 0; mt < 2; mt++) {
            ldm_x4(aHi0 + mt * (16 * PITCH * 2) + kb,
                   ahi[mt][0], ahi[mt][1], ahi[mt][2], ahi[mt][3]);
            ldm_x4(aLo0 + mt * (16 * PITCH * 2) + kb,
                   alo[mt][0], alo[mt][1], alo[mt][2], alo[mt][3]);
        }
        uint32_t bhi[6][2], blo[6][2];
        #pragma unroll
        for (int p = 0; p < 3; p++) {
            ldm_x4(bHi0 + p * (16 * PITCH * 2) + kb,
                   bhi[2 * p][0], bhi[2 * p][1], bhi[2 * p + 1][0], bhi[2 * p + 1][1]);
            ldm_x4(bLo0 + p * (16 * PITCH * 2) + kb,
                   blo[2 * p][0], blo[2 * p][1], blo[2 * p + 1][0], blo[2 * p + 1][1]);
        }

        #pragma unroll
        for (int nt = 0; nt < 6; nt++)
            #pragma unroll
            for (int mt = 0; mt < 2; mt++) {
                mma_bf16(acc[mt][nt], ahi[mt], bhi[nt]);
                mma_bf16(acc[mt][nt], ahi[mt], blo[nt]);
                mma_bf16(acc[mt][nt], alo[mt], bhi[nt]);
            }
    }

    #pragma unroll
    for (int nt = 0; nt < 6; nt++) {
        int col = n0 + warp_n * 48 + nt * 8 + (lane & 3) * 2;
        float b0 = __ldg(bias + col), b1 = __ldg(bias + col + 1);
        #pragma unroll
        for (int mt = 0; mt < 2; mt++) {
            int row0 = m0 + warp_m * 32 + mt * 16 + (lane >> 2);
            float2 v0 = make_float2(acc[mt][nt][0] + b0, acc[mt][nt][1] + b1);
            float2 v1 = make_float2(acc[mt][nt][2] + b0, acc[mt][nt][3] + b1);
            *(float2*)(out + (size_t)row0 * oldd + col)       = v0;
            *(float2*)(out + (size_t)(row0 + 8) * oldd + col) = v1;
        }
    }
}

#define GEMM_MMA_SMEM ((2 * 128 * PITCH + 2 * 96 * PITCH) * (int)sizeof(__nv_bfloat16)) // 93184

// ---------------------------------------------------------------------------
// Tensor-core fused attention + lepe per (window, head).
// R13 changes: no p-split (PV 2-term: ph*vh + ph*vl), cvt.rn.bf16x2 packs,
// ex2.approx with log2e folded into Q scale, ldmatrix.x2.trans for d16-23.
// ---------------------------------------------------------------------------
#define AP 40
#define ASM_Q  0
#define ASM_K  (256 * AP)
#define ASM_VH (512 * AP)
#define ASM_VL (768 * AP)
#define ATT_SMEM (1024 * AP * 2)      // 81920 bytes

__global__ __launch_bounds__(256, 2)
void attn_mma(const float* __restrict__ qkv, const float* __restrict__ pe_w,
              const float* __restrict__ pe_b, float* __restrict__ og)
{
    extern __shared__ __nv_bfloat16 asm_bf[];
    __nv_bfloat16* Qs = asm_bf + ASM_Q;
    __nv_bfloat16* Ks = asm_bf + ASM_K;
    __nv_bfloat16* Vh = asm_bf + ASM_VH;
    __nv_bfloat16* Vl = asm_bf + ASM_VL;

    const int tid  = threadIdx.x;
    const int lane = tid & 31;
    const int warp = tid >> 5;
    const int n    = blockIdx.x;
    const int h    = blockIdx.y;
    const int b    = n >> 8;
    const int rowbase = ((n >> 4) & 15) * 16;
    const int colbase = (n & 15) * 16;

    auto tok = [&](int s) -> int {
        int r = s >> 4, c = s & 15;
        return b * 65536 + (rowbase + r) * 256 + (colbase + c);
    };

    #pragma unroll
    for (int i = tid; i < ATT_SMEM / 16; i += 256)
        ((uint4*)asm_bf)[i] = make_uint4(0, 0, 0, 0);
    __syncthreads();

    // scale * log2(e) folded into Q; softmax exp -> ex2
    const float s2 = 0.29448899158937f; // (1/sqrt(24)) * log2(e)

    #pragma unroll
    for (int it = 0; it < 6; it++) {
        int idx = tid + it * 256;
        int s = idx / 6, qd = idx - s * 6;
        size_t base = (size_t)tok(s) * C3 + h * 72;
        float4 q = *(const float4*)(qkv + base + qd * 4);
        float4 k = *(const float4*)(qkv + base + 24 + qd * 4);
        float4 v = *(const float4*)(qkv + base + 48 + qd * 4);
        uint2 qp = make_uint2(cvt_bf16x2(q.y * s2, q.x * s2),
                              cvt_bf16x2(q.w * s2, q.z * s2));
        uint2 kp = make_uint2(cvt_bf16x2(k.y, k.x), cvt_bf16x2(k.w, k.z));
        __nv_bfloat16 h0, h1, h2, h3, l0, l1, l2, l3;
        bf16split(v.x, h0, l0); bf16split(v.y, h1, l1);
        bf16split(v.z, h2, l2); bf16split(v.w, h3, l3);
        uint2 vhp = make_uint2(pack_bf2(h0, h1), pack_bf2(h2, h3));
        uint2 vlp = make_uint2(pack_bf2(l0, l1), pack_bf2(l2, l3));
        *(uint2*)(Qs + s * AP + qd * 4) = qp;
        *(uint2*)(Ks + s * AP + qd * 4) = kp;
        *(uint2*)(Vh + s * AP + qd * 4) = vhp;
        *(uint2*)(Vl + s * AP + qd * 4) = vlp;
    }
    __syncthreads();

    uint32_t qa[2][2][4];
    #pragma unroll
    for (int mt = 0; mt < 2; mt++)
        #pragma unroll
        for (int kc = 0; kc < 2; kc++) {
            uint32_t addr = smem_u32(Qs + (warp * 32 + mt * 16 + (lane & 15)) * AP
                                        + kc * 16 + (lane >> 4) * 8);
            ldm_x4(addr, qa[mt][kc][0], qa[mt][kc][1], qa[mt][kc][2], qa[mt][kc][3]);
        }

    float O[2][3][4];
    #pragma unroll
    for (int mt = 0; mt < 2; mt++)
        #pragma unroll
        for (int dt = 0; dt < 3; dt++)
            #pragma unroll
            for (int q = 0; q < 4; q++) O[mt][dt][q] = 0.f;
    float lsum[2][2] = {{0.f, 0.f}, {0.f, 0.f}};

    const uint32_t k_row8 = (lane & 7) + ((lane >> 4) << 3);
    const uint32_t k_koff = ((lane >> 3) & 1) * 8;
    const uint32_t v_row8 = (lane & 7) + ((lane >> 3) & 1) * 8;
    const uint32_t v_dcol = ((lane >> 4) & 1) * 8;
    const uint32_t v_row2 = (lane & 15);   // x2.trans: lanes 0-15 address rows

    for (int kb = 0; kb < 16; kb++) {
        uint32_t kf[2][2][2];
        #pragma unroll
        for (int kc = 0; kc < 2; kc++) {
            uint32_t addr = smem_u32(Ks + (kb * 16 + k_row8) * AP + kc * 16 + k_koff);
            ldm_x4(addr, kf[0][kc][0], kf[0][kc][1], kf[1][kc][0], kf[1][kc][1]);
        }

        float S[2][2][4];
        #pragma unroll
        for (int mt = 0; mt < 2; mt++)
            #pragma unroll
            for (int nt = 0; nt < 2; nt++) {
                #pragma unroll
                for (int q = 0; q < 4; q++) S[mt][nt][q] = 0.f;
                mma_bf16(S[mt][nt], qa[mt][0], kf[nt][0]);
                mma_bf16(S[mt][nt], qa[mt][1], kf[nt][1]);
            }

        // softmax numerator (ex2) + row sums + P fragments (plain bf16)
        uint32_t ph[2][4];
        #pragma unroll
        for (int mt = 0; mt < 2; mt++) {
            float p[2][4];
            #pragma unroll
            for (int nt = 0; nt < 2; nt++) {
                #pragma unroll
                for (int q = 0; q < 4; q++) p[nt][q] = ex2f(S[mt][nt][q]);
                lsum[mt][0] += p[nt][0] + p[nt][1];
                lsum[mt][1] += p[nt][2] + p[nt][3];
            }
            ph[mt][0] = cvt_bf16x2(p[0][1], p[0][0]);
            ph[mt][1] = cvt_bf16x2(p[0][3], p[0][2]);
            ph[mt][2] = cvt_bf16x2(p[1][1], p[1][0]);
            ph[mt][3] = cvt_bf16x2(p[1][3], p[1][2]);
        }

        // V fragments: x4.trans for d0-15, x2.trans for d16-23
        uint32_t vhf[3][2], vlf[3][2];
        {
            uint32_t ah = smem_u32(Vh + (kb * 16 + v_row8) * AP + v_dcol);
            uint32_t al = smem_u32(Vl + (kb * 16 + v_row8) * AP + v_dcol);
            ldm_x4_trans(ah, vhf[0][0], vhf[0][1], vhf[1][0], vhf[1][1]);
            ldm_x4_trans(al, vlf[0][0], vlf[0][1], vlf[1][0], vlf[1][1]);
            uint32_t ah2 = smem_u32(Vh + (kb * 16 + v_row2) * AP + 16);
            uint32_t al2 = smem_u32(Vl + (kb * 16 + v_row2) * AP + 16);
            ldm_x2_trans(ah2, vhf[2][0], vhf[2][1]);
            ldm_x2_trans(al2, vlf[2][0], vlf[2][1]);
        }

        // O += P V  (ph*vh + ph*vl)
        #pragma unroll
        for (int mt = 0; mt < 2; mt++)
            #pragma unroll
            for (int dt = 0; dt < 3; dt++) {
                mma_bf16(O[mt][dt], ph[mt], vhf[dt]);
                mma_bf16(O[mt][dt], ph[mt], vlf[dt]);
            }
    }

    float inv[2][2];
    #pragma unroll
    for (int mt = 0; mt < 2; mt++)
        #pragma unroll
        for (int r = 0; r < 2; r++) {
            float v = lsum[mt][r];
            v += __shfl_xor_sync(0xffffffff, v, 1);
            v += __shfl_xor_sync(0xffffffff, v, 2);
            inv[mt][r] = 1.0f / v;
        }

    __syncthreads();
    float* osm = (float*)asm_bf;    // overlays dead Q/K region [256][24]
    #pragma unroll
    for (int mt = 0; mt < 2; mt++) {
        int row = warp * 32 + mt * 16 + (lane >> 2);
        #pragma unroll
        for (int dt = 0; dt < 3; dt++) {
            int col = dt * 8 + (lane & 3) * 2;
            *(float2*)(osm + row * 24 + col) =
                make_float2(O[mt][dt][0] * inv[mt][0], O[mt][dt][1] * inv[mt][0]);
            *(float2*)(osm + (row + 8) * 24 + col) =
                make_float2(O[mt][dt][2] * inv[mt][1], O[mt][dt][3] * inv[mt][1]);
        }
    }
    __syncthreads();

    {
        int s = tid;
        float o[24];
        #pragma unroll
        for (int i = 0; i < 6; i++) {
            float4 v4 = *(float4*)(osm + s * 24 + i * 4);
            o[4 * i] = v4.x; o[4 * i + 1] = v4.y; o[4 * i + 2] = v4.z; o[4 * i + 3] = v4.w;
        }
        int r = s >> 4, c = s & 15;
        #pragma unroll
        for (int ky = -1; ky <= 1; ky++) {
            int r2 = r + ky;
            if (r2 < 0 || r2 > 15) continue;
            #pragma unroll
            for (int kx = -1; kx <= 1; kx++) {
                int c2 = c + kx;
                if (c2 < 0 || c2 > 15) continue;
                const uint32_t* vh2 = (const uint32_t*)(Vh + (r2 * 16 + c2) * AP);
                const uint32_t* vl2 = (const uint32_t*)(Vl + (r2 * 16 + c2) * AP);
                const float* wrow = pe_w + ((ky + 1) * 3 + (kx + 1)) * CH + h * HD;
                #pragma unroll
                for (int i = 0; i < 12; i++) {
                    __nv_bfloat162 hb = *(const __nv_bfloat162*)&vh2[i];
                    __nv_bfloat162 lb = *(const __nv_bfloat162*)&vl2[i];
                    float2 hf = __bfloat1622float2(hb);
                    float2 lf = __bfloat1622float2(lb);
                    o[2 * i]     += (hf.x + lf.x) * __ldg(wrow + 2 * i);
                    o[2 * i + 1] += (hf.y + lf.y) * __ldg(wrow + 2 * i + 1);
                }
            }
        }
        #pragma unroll
        for (int d = 0; d < 24; d++) o[d] += __ldg(pe_b + h * HD + d);

        float4* dst = (float4*)(og + (size_t)tok(s) * CH + h * HD);
        #pragma unroll
        for (int i = 0; i < 6; i++)
            dst[i] = make_float4(o[4 * i], o[4 * i + 1], o[4 * i + 2], o[4 * i + 3]);
    }
}

// ---------------------------------------------------------------------------
extern "C" void kernel_launch(void* const* d_in, const int* in_sizes, int n_in,
                              void* d_out, int out_size)
{
    const float* x     = (const float*)d_in[0];
    const float* qkv_w = (const float*)d_in[1];
    const float* qkv_b = (const float*)d_in[2];
    const float* pe_w  = (const float*)d_in[3];
    const float* pe_b  = (const float*)d_in[4];
    const float* out_w = (const float*)d_in[5];
    const float* out_b = (const float*)d_in[6];
    float* out = (float*)d_out;

    float* qkv_ptr = nullptr;
    float* o_ptr   = nullptr;
    cudaGetSymbolAddress((void**)&qkv_ptr, g_qkv);
    cudaGetSymbolAddress((void**)&o_ptr,   g_o);

    cudaFuncSetAttribute(gemm_mma, cudaFuncAttributeMaxDynamicSharedMemorySize, GEMM_MMA_SMEM);
    cudaFuncSetAttribute(attn_mma, cudaFuncAttributeMaxDynamicSharedMemorySize, ATT_SMEM);

    gemm_mma<<<dim3(NTOK / 128, 3), 256, GEMM_MMA_SMEM>>>(x, qkv_w, qkv_b, qkv_ptr, C3, C3);
    attn_mma<<<dim3(NWIN, NHEADS), 256, ATT_SMEM>>>(qkv_ptr, pe_w, pe_b, o_ptr);
    gemm_mma<<<dim3(NTOK / 128, 1), 256, GEMM_MMA_SMEM>>>(o_ptr, out_w, out_b, out, CH, CH);
}

// round 14
// speedup vs baseline: 2.9026x; 1.1111x over previous
#include <cuda_runtime.h>
#include <cuda_bf16.h>
#include <cstdint>

#define BATCH   2
#define HIMG    256
#define WIMG    256
#define CH      96
#define C3      288
#define WINSZ   16
#define SEQ     256
#define NHEADS  4
#define HD      24
#define NWIN    512
#define NTOK    131072

typedef unsigned long long ull;

__device__ float g_qkv[(size_t)NTOK * C3];
__device__ float g_o  [(size_t)NTOK * CH];

// ---------------- mma helpers ------------------------------------------------
__device__ __forceinline__ uint32_t smem_u32(const void* p) {
    uint32_t a;
    asm("{ .reg .u64 t; cvta.to.shared.u64 t, %1; cvt.u32.u64 %0, t; }" : "=r"(a) : "l"(p));
    return a;
}
__device__ __forceinline__ void ldm_x4(uint32_t addr, uint32_t& r0, uint32_t& r1,
                                       uint32_t& r2, uint32_t& r3) {
    asm volatile("ldmatrix.sync.aligned.m8n8.x4.shared.b16 {%0,%1,%2,%3}, [%4];"
                 : "=r"(r0), "=r"(r1), "=r"(r2), "=r"(r3) : "r"(addr));
}
__device__ __forceinline__ void ldm_x4_trans(uint32_t addr, uint32_t& r0, uint32_t& r1,
                                             uint32_t& r2, uint32_t& r3) {
    asm volatile("ldmatrix.sync.aligned.m8n8.x4.trans.shared.b16 {%0,%1,%2,%3}, [%4];"
                 : "=r"(r0), "=r"(r1), "=r"(r2), "=r"(r3) : "r"(addr));
}
__device__ __forceinline__ void ldm_x2_trans(uint32_t addr, uint32_t& r0, uint32_t& r1) {
    asm volatile("ldmatrix.sync.aligned.m8n8.x2.trans.shared.b16 {%0,%1}, [%2];"
                 : "=r"(r0), "=r"(r1) : "r"(addr));
}
__device__ __forceinline__ void mma_bf16(float* c, const uint32_t* a, const uint32_t* b) {
    asm volatile(
        "mma.sync.aligned.m16n8k16.row.col.f32.bf16.bf16.f32 "
        "{%0,%1,%2,%3}, {%4,%5,%6,%7}, {%8,%9}, {%0,%1,%2,%3};"
        : "+f"(c[0]), "+f"(c[1]), "+f"(c[2]), "+f"(c[3])
        : "r"(a[0]), "r"(a[1]), "r"(a[2]), "r"(a[3]), "r"(b[0]), "r"(b[1]));
}
__device__ __forceinline__ void bf16split(float v, __nv_bfloat16& h, __nv_bfloat16& l) {
    h = __float2bfloat16(v);
    l = __float2bfloat16(v - __bfloat162float(h));
}
__device__ __forceinline__ uint32_t pack_bf2(__nv_bfloat16 a, __nv_bfloat16 b) {
    __nv_bfloat162 t(a, b);
    return *reinterpret_cast<uint32_t*>(&t);
}
__device__ __forceinline__ uint32_t cvt_bf16x2(float hi, float lo) {
    uint32_t r; asm("cvt.rn.bf16x2.f32 %0, %1, %2;" : "=r"(r) : "f"(hi), "f"(lo)); return r;
}
__device__ __forceinline__ float ex2f(float x) {
    float y; asm("ex2.approx.f32 %0, %1;" : "=f"(y) : "f"(x)); return y;
}

// ---------------------------------------------------------------------------
// Tensor-core GEMM (mma.sync bf16, 3-term split).
// R14: N-tiles looped inside the CTA — A tile loaded+converted ONCE, then
// per tile {convert B, MMA, epilogue}. Removes the 3x redundant A DRAM reads
// and A-convert work the 3-N-tile grid had (L1=58.5% was the binder).
// ---------------------------------------------------------------------------
#define PITCH 104

__global__ __launch_bounds__(256, 2)
void gemm_mma(const float* __restrict__ A, const float* __restrict__ W,
              const float* __restrict__ bias, float* __restrict__ out,
              int wld, int oldd, int ntiles)
{
    extern __shared__ __nv_bfloat16 smbf[];
    __nv_bfloat16* Ahi = smbf;
    __nv_bfloat16* Alo = Ahi + 128 * PITCH;
    __nv_bfloat16* Bhi = Alo + 128 * PITCH;
    __nv_bfloat16* Blo = Bhi + 96 * PITCH;

    const int tid  = threadIdx.x;
    const int lane = tid & 31;
    const int wid  = tid >> 5;
    const int m0   = blockIdx.x * 128;

    // ---- convert A tile ONCE: 128 rows x 96 floats -> hi/lo bf16 ----
    #pragma unroll
    for (int it = 0; it < 12; it++) {
        int idx = tid + it * 256;
        int m = idx / 24, q = idx - m * 24;
        float4 v = *(const float4*)(A + (size_t)(m0 + m) * CH + q * 4);
        __nv_bfloat16 h0, h1, h2, h3, l0, l1, l2, l3;
        bf16split(v.x, h0, l0); bf16split(v.y, h1, l1);
        bf16split(v.z, h2, l2); bf16split(v.w, h3, l3);
        uint2 hp = make_uint2(pack_bf2(h0, h1), pack_bf2(h2, h3));
        uint2 lp = make_uint2(pack_bf2(l0, l1), pack_bf2(l2, l3));
        *(uint2*)(Ahi + m * PITCH + q * 4) = hp;
        *(uint2*)(Alo + m * PITCH + q * 4) = lp;
    }

    const int warp_m = wid & 3;
    const int warp_n = wid >> 2;

    const uint32_t a_row  = warp_m * 32 + (lane & 15);
    const uint32_t a_koff = (lane >> 4) * 8;
    const uint32_t aHi0 = smem_u32(Ahi + a_row * PITCH + a_koff);
    const uint32_t aLo0 = smem_u32(Alo + a_row * PITCH + a_koff);
    const uint32_t b_nrow = warp_n * 48 + (lane & 7) + ((lane >> 4) << 3);
    const uint32_t b_koff = ((lane >> 3) & 1) * 8;
    const uint32_t bHi0 = smem_u32(Bhi + b_nrow * PITCH + b_koff);
    const uint32_t bLo0 = smem_u32(Blo + b_nrow * PITCH + b_koff);

    for (int t = 0; t < ntiles; t++) {
        const int n0 = t * 96;
        if (t) __syncthreads();   // prior tile's ldmatrix must finish before B overwrite

        // ---- convert B tile: W[k][n0+n] -> Bs[n][k] hi/lo ----
        #pragma unroll
        for (int it = 0; it < 9; it++) {
            int idx = tid + it * 256;
            int kq = idx / 96, n = idx - kq * 96;
            int kbase = kq * 4;
            float w0 = W[(size_t)(kbase + 0) * wld + n0 + n];
            float w1 = W[(size_t)(kbase + 1) * wld + n0 + n];
            float w2 = W[(size_t)(kbase + 2) * wld + n0 + n];
            float w3 = W[(size_t)(kbase + 3) * wld + n0 + n];
            __nv_bfloat16 h0, h1, h2, h3, l0, l1, l2, l3;
            bf16split(w0, h0, l0); bf16split(w1, h1, l1);
            bf16split(w2, h2, l2); bf16split(w3, h3, l3);
            uint2 hp = make_uint2(pack_bf2(h0, h1), pack_bf2(h2, h3));
            uint2 lp = make_uint2(pack_bf2(l0, l1), pack_bf2(l2, l3));
            *(uint2*)(Bhi + n * PITCH + kbase) = hp;
            *(uint2*)(Blo + n * PITCH + kbase) = lp;
        }
        __syncthreads();

        float acc[2][6][4];
        #pragma unroll
        for (int i = 0; i < 2; i++)
            #pragma unroll
            for (int j = 0; j < 6; j++)
                #pragma unroll
                for (int q = 0; q < 4; q++) acc[i][j][q] = 0.f;

        #pragma unroll
        for (int c = 0; c < 6; c++) {
            const uint32_t kb = c * 32;

            uint32_t ahi[2][4], alo[2][4];
            #pragma unroll
            for (int mt = 0; mt < 2; mt++) {
                ldm_x4(aHi0 + mt * (16 * PITCH * 2) + kb,
                       ahi[mt][0], ahi[mt][1], ahi[mt][2], ahi[mt][3]);
                ldm_x4(aLo0 + mt * (16 * PITCH * 2) + kb,
                       alo[mt][0], alo[mt][1], alo[mt][2], alo[mt][3]);
            }
            uint32_t bhi[6][2], blo[6][2];
            #pragma unroll
            for (int p = 0; p < 3; p++) {
                ldm_x4(bHi0 + p * (16 * PITCH * 2) + kb,
                       bhi[2 * p][0], bhi[2 * p][1], bhi[2 * p + 1][0], bhi[2 * p + 1][1]);
                ldm_x4(bLo0 + p * (16 * PITCH * 2) + kb,
                       blo[2 * p][0], blo[2 * p][1], blo[2 * p + 1][0], blo[2 * p + 1][1]);
            }

            #pragma unroll
            for (int nt = 0; nt < 6; nt++)
                #pragma unroll
                for (int mt = 0; mt < 2; mt++) {
                    mma_bf16(acc[mt][nt], ahi[mt], bhi[nt]);
                    mma_bf16(acc[mt][nt], ahi[mt], blo[nt]);
                    mma_bf16(acc[mt][nt], alo[mt], bhi[nt]);
                }
        }

        #pragma unroll
        for (int nt = 0; nt < 6; nt++) {
            int col = n0 + warp_n * 48 + nt * 8 + (lane & 3) * 2;
            float b0 = __ldg(bias + col), b1 = __ldg(bias + col + 1);
            #pragma unroll
            for (int mt = 0; mt < 2; mt++) {
                int row0 = m0 + warp_m * 32 + mt * 16 + (lane >> 2);
                float2 v0 = make_float2(acc[mt][nt][0] + b0, acc[mt][nt][1] + b1);
                float2 v1 = make_float2(acc[mt][nt][2] + b0, acc[mt][nt][3] + b1);
                *(float2*)(out + (size_t)row0 * oldd + col)       = v0;
                *(float2*)(out + (size_t)(row0 + 8) * oldd + col) = v1;
            }
        }
    }
}

#define GEMM_MMA_SMEM ((2 * 128 * PITCH + 2 * 96 * PITCH) * (int)sizeof(__nv_bfloat16)) // 93184

// ---------------------------------------------------------------------------
// Tensor-core fused attention + lepe per (window, head).
// R14: zero only pad columns 24..31 (the only pad ldmatrix reads) instead of
// the full 80KB smem.
// ---------------------------------------------------------------------------
#define AP 40
#define ASM_Q  0
#define ASM_K  (256 * AP)
#define ASM_VH (512 * AP)
#define ASM_VL (768 * AP)
#define ATT_SMEM (1024 * AP * 2)      // 81920 bytes

__global__ __launch_bounds__(256, 2)
void attn_mma(const float* __restrict__ qkv, const float* __restrict__ pe_w,
              const float* __restrict__ pe_b, float* __restrict__ og)
{
    extern __shared__ __nv_bfloat16 asm_bf[];
    __nv_bfloat16* Qs = asm_bf + ASM_Q;
    __nv_bfloat16* Ks = asm_bf + ASM_K;
    __nv_bfloat16* Vh = asm_bf + ASM_VH;
    __nv_bfloat16* Vl = asm_bf + ASM_VL;

    const int tid  = threadIdx.x;
    const int lane = tid & 31;
    const int warp = tid >> 5;
    const int n    = blockIdx.x;
    const int h    = blockIdx.y;
    const int b    = n >> 8;
    const int rowbase = ((n >> 4) & 15) * 16;
    const int colbase = (n & 15) * 16;

    auto tok = [&](int s) -> int {
        int r = s >> 4, c = s & 15;
        return b * 65536 + (rowbase + r) * 256 + (colbase + c);
    };

    // ---- zero ONLY pad columns 24..31 of each 40-wide row (1024 rows) ----
    #pragma unroll
    for (int i = tid; i < 1024; i += 256)
        *(uint4*)(asm_bf + i * AP + 24) = make_uint4(0, 0, 0, 0);
    __syncthreads();

    const float s2 = 0.29448899158937f; // (1/sqrt(24)) * log2(e)

    #pragma unroll
    for (int it = 0; it < 6; it++) {
        int idx = tid + it * 256;
        int s = idx / 6, qd = idx - s * 6;
        size_t base = (size_t)tok(s) * C3 + h * 72;
        float4 q = *(const float4*)(qkv + base + qd * 4);
        float4 k = *(const float4*)(qkv + base + 24 + qd * 4);
        float4 v = *(const float4*)(qkv + base + 48 + qd * 4);
        uint2 qp = make_uint2(cvt_bf16x2(q.y * s2, q.x * s2),
                              cvt_bf16x2(q.w * s2, q.z * s2));
        uint2 kp = make_uint2(cvt_bf16x2(k.y, k.x), cvt_bf16x2(k.w, k.z));
        __nv_bfloat16 h0, h1, h2, h3, l0, l1, l2, l3;
        bf16split(v.x, h0, l0); bf16split(v.y, h1, l1);
        bf16split(v.z, h2, l2); bf16split(v.w, h3, l3);
        uint2 vhp = make_uint2(pack_bf2(h0, h1), pack_bf2(h2, h3));
        uint2 vlp = make_uint2(pack_bf2(l0, l1), pack_bf2(l2, l3));
        *(uint2*)(Qs + s * AP + qd * 4) = qp;
        *(uint2*)(Ks + s * AP + qd * 4) = kp;
        *(uint2*)(Vh + s * AP + qd * 4) = vhp;
        *(uint2*)(Vl + s * AP + qd * 4) = vlp;
    }
    __syncthreads();

    uint32_t qa[2][2][4];
    #pragma unroll
    for (int mt = 0; mt < 2; mt++)
        #pragma unroll
        for (int kc = 0; kc < 2; kc++) {
            uint32_t addr = smem_u32(Qs + (warp * 32 + mt * 16 + (lane & 15)) * AP
                                        + kc * 16 + (lane >> 4) * 8);
            ldm_x4(addr, qa[mt][kc][0], qa[mt][kc][1], qa[mt][kc][2], qa[mt][kc][3]);
        }

    float O[2][3][4];
    #pragma unroll
    for (int mt = 0; mt < 2; mt++)
        #pragma unroll
        for (int dt = 0; dt < 3; dt++)
            #pragma unroll
            for (int q = 0; q < 4; q++) O[mt][dt][q] = 0.f;
    float lsum[2][2] = {{0.f, 0.f}, {0.f, 0.f}};

    const uint32_t k_row8 = (lane & 7) + ((lane >> 4) << 3);
    const uint32_t k_koff = ((lane >> 3) & 1) * 8;
    const uint32_t v_row8 = (lane & 7) + ((lane >> 3) & 1) * 8;
    const uint32_t v_dcol = ((lane >> 4) & 1) * 8;
    const uint32_t v_row2 = (lane & 15);

    for (int kb = 0; kb < 16; kb++) {
        uint32_t kf[2][2][2];
        #pragma unroll
        for (int kc = 0; kc < 2; kc++) {
            uint32_t addr = smem_u32(Ks + (kb * 16 + k_row8) * AP + kc * 16 + k_koff);
            ldm_x4(addr, kf[0][kc][0], kf[0][kc][1], kf[1][kc][0], kf[1][kc][1]);
        }

        float S[2][2][4];
        #pragma unroll
        for (int mt = 0; mt < 2; mt++)
            #pragma unroll
            for (int nt = 0; nt < 2; nt++) {
                #pragma unroll
                for (int q = 0; q < 4; q++) S[mt][nt][q] = 0.f;
                mma_bf16(S[mt][nt], qa[mt][0], kf[nt][0]);
                mma_bf16(S[mt][nt], qa[mt][1], kf[nt][1]);
            }

        uint32_t ph[2][4];
        #pragma unroll
        for (int mt = 0; mt < 2; mt++) {
            float p[2][4];
            #pragma unroll
            for (int nt = 0; nt < 2; nt++) {
                #pragma unroll
                for (int q = 0; q < 4; q++) p[nt][q] = ex2f(S[mt][nt][q]);
                lsum[mt][0] += p[nt][0] + p[nt][1];
                lsum[mt][1] += p[nt][2] + p[nt][3];
            }
            ph[mt][0] = cvt_bf16x2(p[0][1], p[0][0]);
            ph[mt][1] = cvt_bf16x2(p[0][3], p[0][2]);
            ph[mt][2] = cvt_bf16x2(p[1][1], p[1][0]);
            ph[mt][3] = cvt_bf16x2(p[1][3], p[1][2]);
        }

        uint32_t vhf[3][2], vlf[3][2];
        {
            uint32_t ah = smem_u32(Vh + (kb * 16 + v_row8) * AP + v_dcol);
            uint32_t al = smem_u32(Vl + (kb * 16 + v_row8) * AP + v_dcol);
            ldm_x4_trans(ah, vhf[0][0], vhf[0][1], vhf[1][0], vhf[1][1]);
            ldm_x4_trans(al, vlf[0][0], vlf[0][1], vlf[1][0], vlf[1][1]);
            uint32_t ah2 = smem_u32(Vh + (kb * 16 + v_row2) * AP + 16);
            uint32_t al2 = smem_u32(Vl + (kb * 16 + v_row2) * AP + 16);
            ldm_x2_trans(ah2, vhf[2][0], vhf[2][1]);
            ldm_x2_trans(al2, vlf[2][0], vlf[2][1]);
        }

        #pragma unroll
        for (int mt = 0; mt < 2; mt++)
            #pragma unroll
            for (int dt = 0; dt < 3; dt++) {
                mma_bf16(O[mt][dt], ph[mt], vhf[dt]);
                mma_bf16(O[mt][dt], ph[mt], vlf[dt]);
            }
    }

    float inv[2][2];
    #pragma unroll
    for (int mt = 0; mt < 2; mt++)
        #pragma unroll
        for (int r = 0; r < 2; r++) {
            float v = lsum[mt][r];
            v += __shfl_xor_sync(0xffffffff, v, 1);
            v += __shfl_xor_sync(0xffffffff, v, 2);
            inv[mt][r] = 1.0f / v;
        }

    __syncthreads();
    float* osm = (float*)asm_bf;    // overlays dead Q/K region [256][24]
    #pragma unroll
    for (int mt = 0; mt < 2; mt++) {
        int row = warp * 32 + mt * 16 + (lane >> 2);
        #pragma unroll
        for (int dt = 0; dt < 3; dt++) {
            int col = dt * 8 + (lane & 3) * 2;
            *(float2*)(osm + row * 24 + col) =
                make_float2(O[mt][dt][0] * inv[mt][0], O[mt][dt][1] * inv[mt][0]);
            *(float2*)(osm + (row + 8) * 24 + col) =
                make_float2(O[mt][dt][2] * inv[mt][1], O[mt][dt][3] * inv[mt][1]);
        }
    }
    __syncthreads();

    {
        int s = tid;
        float o[24];
        #pragma unroll
        for (int i = 0; i < 6; i++) {
            float4 v4 = *(float4*)(osm + s * 24 + i * 4);
            o[4 * i] = v4.x; o[4 * i + 1] = v4.y; o[4 * i + 2] = v4.z; o[4 * i + 3] = v4.w;
        }
        int r = s >> 4, c = s & 15;
        #pragma unroll
        for (int ky = -1; ky <= 1; ky++) {
            int r2 = r + ky;
            if (r2 < 0 || r2 > 15) continue;
            #pragma unroll
            for (int kx = -1; kx <= 1; kx++) {
                int c2 = c + kx;
                if (c2 < 0 || c2 > 15) continue;
                const uint32_t* vh2 = (const uint32_t*)(Vh + (r2 * 16 + c2) * AP);
                const uint32_t* vl2 = (const uint32_t*)(Vl + (r2 * 16 + c2) * AP);
                const float* wrow = pe_w + ((ky + 1) * 3 + (kx + 1)) * CH + h * HD;
                #pragma unroll
                for (int i = 0; i < 12; i++) {
                    __nv_bfloat162 hb = *(const __nv_bfloat162*)&vh2[i];
                    __nv_bfloat162 lb = *(const __nv_bfloat162*)&vl2[i];
                    float2 hf = __bfloat1622float2(hb);
                    float2 lf = __bfloat1622float2(lb);
                    o[2 * i]     += (hf.x + lf.x) * __ldg(wrow + 2 * i);
                    o[2 * i + 1] += (hf.y + lf.y) * __ldg(wrow + 2 * i + 1);
                }
            }
        }
        #pragma unroll
        for (int d = 0; d < 24; d++) o[d] += __ldg(pe_b + h * HD + d);

        float4* dst = (float4*)(og + (size_t)tok(s) * CH + h * HD);
        #pragma unroll
        for (int i = 0; i < 6; i++)
            dst[i] = make_float4(o[4 * i], o[4 * i + 1], o[4 * i + 2], o[4 * i + 3]);
    }
}

// ---------------------------------------------------------------------------
extern "C" void kernel_launch(void* const* d_in, const int* in_sizes, int n_in,
                              void* d_out, int out_size)
{
    const float* x     = (const float*)d_in[0];
    const float* qkv_w = (const float*)d_in[1];
    const float* qkv_b = (const float*)d_in[2];
    const float* pe_w  = (const float*)d_in[3];
    const float* pe_b  = (const float*)d_in[4];
    const float* out_w = (const float*)d_in[5];
    const float* out_b = (const float*)d_in[6];
    float* out = (float*)d_out;

    float* qkv_ptr = nullptr;
    float* o_ptr   = nullptr;
    cudaGetSymbolAddress((void**)&qkv_ptr, g_qkv);
    cudaGetSymbolAddress((void**)&o_ptr,   g_o);

    cudaFuncSetAttribute(gemm_mma, cudaFuncAttributeMaxDynamicSharedMemorySize, GEMM_MMA_SMEM);
    cudaFuncSetAttribute(attn_mma, cudaFuncAttributeMaxDynamicSharedMemorySize, ATT_SMEM);

    // 1) QKV projection: A converted once per CTA, 3 N-tiles looped inside
    gemm_mma<<<dim3(NTOK / 128, 1), 256, GEMM_MMA_SMEM>>>(x, qkv_w, qkv_b, qkv_ptr, C3, C3, 3);

    // 2) Fused windowed attention + lepe (mma.sync)
    attn_mma<<<dim3(NWIN, NHEADS), 256, ATT_SMEM>>>(qkv_ptr, pe_w, pe_b, o_ptr);

    // 3) Output projection: 1 N-tile
    gemm_mma<<<dim3(NTOK / 128, 1), 256, GEMM_MMA_SMEM>>>(o_ptr, out_w, out_b, out, CH, CH, 1);
}